// round 6
// baseline (speedup 1.0000x reference)
#include <cuda_runtime.h>
#include <math.h>

// ---------------------------------------------------------------------------
// FCOS head, fp32, fully batched across towers and FPN levels.
//   4x [ conv3x3(256->256) -> GN(32) -> ReLU ]  (cls + box towers, 5 levels,
//   all in ONE launch per step), then batched head convs writing directly
//   into the permuted [pixel][85] output.
// ---------------------------------------------------------------------------

#define KTOT 2304          // 256 IC * 9
#define CH   256
#define NPIX 8525          // 80^2+40^2+20^2+10^2+5^2

__device__ float g_raw[2][CH * NPIX];     // per-tower conv output (pre-GN)
__device__ float g_act[2][CH * NPIX];     // per-tower activation (post GN+ReLU)
__device__ float g_stats[2 * 5 * 32 * 2]; // [tower][level][group]{mean,rstd}

__constant__ int   c_Hc[5]      = {80, 40, 20, 10, 5};
__constant__ int   c_HWc[5]     = {6400, 1600, 400, 100, 25};
__constant__ int   c_cumHW[5]   = {0, 6400, 8000, 8400, 8500};
__constant__ int   c_pbCum[5]   = {100, 125, 132, 134, 135}; // 64-px blocks, upper cum
__constant__ int   c_apCum[5]   = {25, 32, 34, 35, 36};      // 256-px blocks, upper cum
__constant__ float c_strideF[5] = {8.f, 16.f, 32.f, 64.f, 128.f};

// ---------------------------------------------------------------------------
// 64(oc) x 64(pix) x 16(k) implicit-GEMM tile, 256 threads, 4x4 microtile.
// As stored [k][oc] (padded) so the inner loop is 2x LDS.128 + 16 FFMA per k.
// Weight rows < split come from w1, >= split from w2 (reindexed).
// ---------------------------------------------------------------------------
__device__ __forceinline__ void gemm64x64(
    const float* __restrict__ in, int H, int W, int HW,
    int pBase, int ocBase, int OC, int split,
    const float* __restrict__ w1, const float* __restrict__ w2,
    float acc[4][4])
{
    __shared__ float As[16][68];   // [k][oc] (+4 pad)
    __shared__ float Bs[16][64];   // [k][pixel]

    const int tid = threadIdx.x;

    int ak[4], aoc[4], bk[4], bp[4], bh[4], bw[4], ic[4], rs[4];
    bool bvld[4];
    const float* wrow[4];
#pragma unroll
    for (int i = 0; i < 4; i++) {
        int idx = tid + i * 256;            // 0..1023
        ak[i]  = idx & 15;                  // consecutive tids -> consecutive k (coalesced gmem)
        aoc[i] = idx >> 4;
        int oc = ocBase + aoc[i];
        wrow[i] = (oc < OC)
            ? ((oc < split) ? w1 + (size_t)oc * KTOT
                            : w2 + (size_t)(oc - split) * KTOT)
            : (const float*)0;
        bk[i] = idx >> 6;                   // 0..15
        bp[i] = idx & 63;
        int pp = pBase + bp[i];
        bvld[i] = (pp < HW);
        int h = bvld[i] ? pp / W : 0;
        bh[i] = h;
        bw[i] = bvld[i] ? pp - h * W : 0;
        ic[i] = bk[i] / 9;                  // 0 or 1
        rs[i] = bk[i] - ic[i] * 9;
    }

    for (int k0 = 0; k0 < KTOT; k0 += 16) {
#pragma unroll
        for (int i = 0; i < 4; i++)
            As[ak[i]][aoc[i]] = wrow[i] ? wrow[i][k0 + ak[i]] : 0.f;
#pragma unroll
        for (int i = 0; i < 4; i++) {
            int r = rs[i] / 3;
            int s = rs[i] - r * 3;
            int row = bh[i] + r - 1;
            int col = bw[i] + s - 1;
            float v = 0.f;
            if (bvld[i] && (unsigned)row < (unsigned)H && (unsigned)col < (unsigned)W)
                v = in[(size_t)ic[i] * HW + row * W + col];
            Bs[bk[i]][bp[i]] = v;
            // advance k by 16 for next tile: ic*9 + rs tracks it
            rs[i] += 16;
            if (rs[i] >= 9) { rs[i] -= 9; ic[i]++; }
            if (rs[i] >= 9) { rs[i] -= 9; ic[i]++; }
        }
        __syncthreads();

        const int tx = tid & 15, ty = tid >> 4;
#pragma unroll
        for (int k = 0; k < 16; k++) {
            float4 a = *(const float4*)&As[k][ty * 4];
            float4 b = *(const float4*)&Bs[k][tx * 4];
            acc[0][0] = fmaf(a.x, b.x, acc[0][0]);
            acc[0][1] = fmaf(a.x, b.y, acc[0][1]);
            acc[0][2] = fmaf(a.x, b.z, acc[0][2]);
            acc[0][3] = fmaf(a.x, b.w, acc[0][3]);
            acc[1][0] = fmaf(a.y, b.x, acc[1][0]);
            acc[1][1] = fmaf(a.y, b.y, acc[1][1]);
            acc[1][2] = fmaf(a.y, b.z, acc[1][2]);
            acc[1][3] = fmaf(a.y, b.w, acc[1][3]);
            acc[2][0] = fmaf(a.z, b.x, acc[2][0]);
            acc[2][1] = fmaf(a.z, b.y, acc[2][1]);
            acc[2][2] = fmaf(a.z, b.z, acc[2][2]);
            acc[2][3] = fmaf(a.z, b.w, acc[2][3]);
            acc[3][0] = fmaf(a.w, b.x, acc[3][0]);
            acc[3][1] = fmaf(a.w, b.y, acc[3][1]);
            acc[3][2] = fmaf(a.w, b.z, acc[3][2]);
            acc[3][3] = fmaf(a.w, b.w, acc[3][3]);
        }
        __syncthreads();
    }
}

__device__ __forceinline__ int decode_level(int bx, const int* cum)
{
    int l = 0;
    if (bx >= cum[0]) l = 1;
    if (bx >= cum[1]) l = 2;
    if (bx >= cum[2]) l = 3;
    if (bx >= cum[3]) l = 4;
    return l;
}

// ---------------------------------------------------------------------------
// Tower conv step: grid (135 pixel-blocks, 4 oc-blocks, 2 towers)
// ---------------------------------------------------------------------------
__global__ __launch_bounds__(256) void tower_conv(
    const float* __restrict__ f0, const float* __restrict__ f1,
    const float* __restrict__ f2, const float* __restrict__ f3,
    const float* __restrict__ f4,
    const float* __restrict__ wCls, const float* __restrict__ wBox,
    const float* __restrict__ bCls, const float* __restrict__ bBox,
    int step)
{
    const int bx = blockIdx.x;
    const int l = decode_level(bx, c_pbCum);
    const int pixBase = (bx - (l ? c_pbCum[l - 1] : 0)) * 64;
    const int H = c_Hc[l], W = H, HW = c_HWc[l];
    const int t = blockIdx.z;
    const int ocBase = blockIdx.y * 64;

    const float* in;
    if (step == 0)
        in = (l == 0) ? f0 : (l == 1) ? f1 : (l == 2) ? f2 : (l == 3) ? f3 : f4;
    else
        in = &g_act[t][(size_t)CH * c_cumHW[l]];

    const float* w = (t ? wBox : wCls) + (size_t)step * CH * KTOT;
    const float* b = (t ? bBox : bCls) + step * CH;

    float acc[4][4] = {};
    gemm64x64(in, H, W, HW, pixBase, ocBase, CH, CH, w, w, acc);

    float* out = &g_raw[t][(size_t)CH * c_cumHW[l]];
    const int tx = threadIdx.x & 15, ty = threadIdx.x >> 4;
#pragma unroll
    for (int i = 0; i < 4; i++) {
        int oc = ocBase + ty * 4 + i;
        float bb = b[oc];
#pragma unroll
        for (int j = 0; j < 4; j++) {
            int p = pixBase + tx * 4 + j;
            if (p < HW) out[(size_t)oc * HW + p] = acc[i][j] + bb;
        }
    }
}

// ---------------------------------------------------------------------------
// Head convs: grid (135, ceil(OC/64)). predMode: oc<4 -> relu(v*scale)*stride,
// oc==4 -> iou passthrough. Writes [pixel][85] layout directly.
// ---------------------------------------------------------------------------
__global__ __launch_bounds__(256) void head_conv(
    const float* __restrict__ w1, const float* __restrict__ w2,
    const float* __restrict__ b1, const float* __restrict__ b2,
    int split, int OC, int tower, int ocOut, int predMode,
    const float* __restrict__ scales,
    float* __restrict__ out)
{
    const int bx = blockIdx.x;
    const int l = decode_level(bx, c_pbCum);
    const int pixBase = (bx - (l ? c_pbCum[l - 1] : 0)) * 64;
    const int H = c_Hc[l], W = H, HW = c_HWc[l];
    const int ocBase = blockIdx.y * 64;

    const float* in = &g_act[tower][(size_t)CH * c_cumHW[l]];

    float acc[4][4] = {};
    gemm64x64(in, H, W, HW, pixBase, ocBase, OC, split, w1, w2, acc);

    float sc = 1.f, sm = 1.f;
    if (predMode) { sc = __ldg(&scales[l]); sm = c_strideF[l]; }

    const int tx = threadIdx.x & 15, ty = threadIdx.x >> 4;
#pragma unroll
    for (int i = 0; i < 4; i++) {
        int oc = ocBase + ty * 4 + i;
        if (oc >= OC) continue;
        float bb = (oc < split) ? b1[oc] : b2[oc - split];
#pragma unroll
        for (int j = 0; j < 4; j++) {
            int p = pixBase + tx * 4 + j;
            if (p >= HW) continue;
            float v = acc[i][j] + bb;
            if (predMode && oc < 4) v = fmaxf(v * sc, 0.f) * sm;
            out[(size_t)(c_cumHW[l] + p) * 85 + ocOut + oc] = v;
        }
    }
}

// ---------------------------------------------------------------------------
// GroupNorm stats: grid (32 groups, 5 levels, 2 towers)
// ---------------------------------------------------------------------------
__global__ __launch_bounds__(256) void gn_stats()
{
    const int g = blockIdx.x, l = blockIdx.y, t = blockIdx.z;
    const int HW = c_HWc[l];
    const float4* x4 = (const float4*)&g_raw[t][(size_t)CH * c_cumHW[l] +
                                               (size_t)g * 8 * HW];
    const int n = 8 * HW;
    const int n4 = n >> 2;

    float s = 0.f, ss = 0.f;
    for (int i = threadIdx.x; i < n4; i += 256) {
        float4 v = x4[i];
        s += (v.x + v.y) + (v.z + v.w);
        ss = fmaf(v.x, v.x, ss);
        ss = fmaf(v.y, v.y, ss);
        ss = fmaf(v.z, v.z, ss);
        ss = fmaf(v.w, v.w, ss);
    }
    __shared__ float sh0[256], sh1[256];
    sh0[threadIdx.x] = s;
    sh1[threadIdx.x] = ss;
    __syncthreads();
    for (int o = 128; o > 0; o >>= 1) {
        if (threadIdx.x < o) {
            sh0[threadIdx.x] += sh0[threadIdx.x + o];
            sh1[threadIdx.x] += sh1[threadIdx.x + o];
        }
        __syncthreads();
    }
    if (threadIdx.x == 0) {
        float inv_n = 1.f / (float)n;
        float mean = sh0[0] * inv_n;
        float var = sh1[0] * inv_n - mean * mean;
        int sidx = ((t * 5 + l) * 32 + g) * 2;
        g_stats[sidx]     = mean;
        g_stats[sidx + 1] = rsqrtf(fmaxf(var, 0.f) + 1e-5f);
    }
}

// ---------------------------------------------------------------------------
// GN apply + ReLU: grid (36 pixel-blocks, 256 channels, 2 towers)
// ---------------------------------------------------------------------------
__global__ __launch_bounds__(256) void gn_apply(
    const float* __restrict__ gwCls, const float* __restrict__ gbCls,
    const float* __restrict__ gwBox, const float* __restrict__ gbBox,
    int step)
{
    const int bx = blockIdx.x;
    const int l = decode_level(bx, c_apCum);
    const int HW = c_HWc[l];
    const int p = (bx - (l ? c_apCum[l - 1] : 0)) * 256 + threadIdx.x;
    if (p >= HW) return;

    const int c = blockIdx.y, t = blockIdx.z;
    const float* gw = (t ? gwBox : gwCls) + step * CH;
    const float* gb = (t ? gbBox : gbCls) + step * CH;

    const int sidx = ((t * 5 + l) * 32 + (c >> 3)) * 2;
    float mean = g_stats[sidx];
    float rstd = g_stats[sidx + 1];
    float ga = gw[c] * rstd;
    float be = fmaf(-mean, ga, gb[c]);

    size_t base = (size_t)CH * c_cumHW[l] + (size_t)c * HW;
    float v = g_raw[t][base + p];
    g_act[t][base + p] = fmaxf(fmaf(v, ga, be), 0.f);
}

// ---------------------------------------------------------------------------
// Host driver: 14 launches total
// ---------------------------------------------------------------------------
extern "C" void kernel_launch(void* const* d_in, const int* in_sizes, int n_in,
                              void* d_out, int out_size)
{
    const float* f0 = (const float*)d_in[0];
    const float* f1 = (const float*)d_in[1];
    const float* f2 = (const float*)d_in[2];
    const float* f3 = (const float*)d_in[3];
    const float* f4 = (const float*)d_in[4];
    const float* cls_w    = (const float*)d_in[5];
    const float* cls_b    = (const float*)d_in[6];
    const float* cls_gn_w = (const float*)d_in[7];
    const float* cls_gn_b = (const float*)d_in[8];
    const float* box_w    = (const float*)d_in[9];
    const float* box_b    = (const float*)d_in[10];
    const float* box_gn_w = (const float*)d_in[11];
    const float* box_gn_b = (const float*)d_in[12];
    const float* score_w  = (const float*)d_in[13];
    const float* score_b  = (const float*)d_in[14];
    const float* pred_w   = (const float*)d_in[15];
    const float* pred_b   = (const float*)d_in[16];
    const float* iou_w    = (const float*)d_in[17];
    const float* iou_b    = (const float*)d_in[18];
    const float* scales   = (const float*)d_in[19];
    float* out = (float*)d_out;

    for (int step = 0; step < 4; step++) {
        tower_conv<<<dim3(135, 4, 2), 256>>>(f0, f1, f2, f3, f4,
                                             cls_w, box_w, cls_b, box_b, step);
        gn_stats<<<dim3(32, 5, 2), 256>>>();
        gn_apply<<<dim3(36, 256, 2), 256>>>(cls_gn_w, cls_gn_b,
                                            box_gn_w, box_gn_b, step);
    }

    // score: 80 channels from cls tower -> cols 0..79
    head_conv<<<dim3(135, 2), 256>>>(score_w, score_w, score_b, score_b,
                                     80, 80, 0, 0, 0, scales, out);
    // pred (4ch, scale+relu+stride) + iou (1ch) from box tower -> cols 80..84
    head_conv<<<dim3(135, 1), 256>>>(pred_w, iou_w, pred_b, iou_b,
                                     4, 5, 1, 80, 1, scales, out);
}

// round 8
// speedup vs baseline: 2.6741x; 2.6741x over previous
#include <cuda_runtime.h>
#include <stdint.h>

#define CH 256
#define NPIX 8525
#define NSLICE 72

// ---- scratch --------------------------------------------------------------
__device__ float g_wT[2][4][2][NSLICE][256][32]; // tower weights hi/lo
__device__ float g_wS[2][NSLICE][128][32];       // score weights (80 used, rest 0)
__device__ float g_wP[2][NSLICE][8][32];         // pred(4)+iou(1)+pad
__device__ float g_featD[2][NPIX * CH];          // features [pix][ch] hi/lo
__device__ float g_actD[2][2][NPIX * CH];        // [tower][hilo][pix*256+c]
__device__ float g_rawD[2][NPIX * CH];           // pre-GN [pix][ch]
__device__ float g_gst[2 * 5 * 32 * 2];

__constant__ int   c_Hc[5]   = {80, 40, 20, 10, 5};
__constant__ int   c_HWc[5]  = {6400, 1600, 400, 100, 25};
__constant__ int   c_cum[5]  = {0, 6400, 8000, 8400, 8500};
__constant__ int   c_tcum[5] = {50, 63, 67, 68, 69};
__constant__ float c_strF[5] = {8.f, 16.f, 32.f, 64.f, 128.f};

__device__ __forceinline__ float f2tf32(float x) {
    uint32_t r; asm("cvt.rna.tf32.f32 %0, %1;" : "=r"(r) : "f"(x));
    return __uint_as_float(r);
}

// D(16x8) += A(16x8) * B(8x8), tf32 inputs, fp32 accum
#define MMA(c, a, b) \
    asm volatile("mma.sync.aligned.m16n8k8.row.col.f32.tf32.tf32.f32 " \
        "{%0,%1,%2,%3},{%4,%5,%6,%7},{%8,%9},{%0,%1,%2,%3};" \
        : "+f"((c)[0]), "+f"((c)[1]), "+f"((c)[2]), "+f"((c)[3]) \
        : "r"((a)[0]), "r"((a)[1]), "r"((a)[2]), "r"((a)[3]), \
          "r"((b)[0]), "r"((b)[1]))

// ---- SMEM: per buffer: Ah[128][36], Al, Bh[128][36], Bl  (floats) ---------
#define A_PITCH 36
#define HL_STRIDE 4608          // 128*36
#define B_BASE 9216             // Bh starts here
#define BUF_FLOATS 18432        // 4 * 4608
#define SMEM_BYTES (2 * BUF_FLOATS * 4)   // 147456

__device__ __forceinline__ int lvl_of_tile(int bx) {
    int l = 0;
    if (bx >= c_tcum[0]) l = 1;
    if (bx >= c_tcum[1]) l = 2;
    if (bx >= c_tcum[2]) l = 3;
    if (bx >= c_tcum[3]) l = 4;
    return l;
}
__device__ __forceinline__ int lvl_of_pix(int p) {
    int l = 0;
    if (p >= 6400) l = 1;
    if (p >= 8000) l = 2;
    if (p >= 8400) l = 3;
    if (p >= 8500) l = 4;
    return l;
}

// ---------------------------------------------------------------------------
// Fill one slice stage: A = im2col rows (128px x 32k, hi/lo),
// B = weights (BROWS x 32k, hi/lo). WROWS = weight array row stride.
// ---------------------------------------------------------------------------
template <int WROWS, int BROWS>
__device__ __forceinline__ void fill_slice(
    float* __restrict__ buf, int s,
    const float* __restrict__ ih, const float* __restrict__ il,
    const float* __restrict__ wb, int ocr0,
    const int* ah, const int* aw, const bool* apv, int H, int W)
{
    const int tid = threadIdx.x;
    const int rs = s >> 3, ic0 = (s & 7) * 32;
    const int dr = rs / 3 - 1, ds = rs % 3 - 1;

    // A phase
    float4 ra[8];
#pragma unroll
    for (int it = 0; it < 8; it++) {
        int slot = tid + it * 256;
        int hilo = slot >> 10;
        int c4 = slot & 7;
        int hh = ah[it] + dr, ww = aw[it] + ds;
        bool ok = apv[it] && (unsigned)hh < (unsigned)H && (unsigned)ww < (unsigned)W;
        float4 v = make_float4(0.f, 0.f, 0.f, 0.f);
        if (ok)
            v = *(const float4*)((hilo ? il : ih) +
                                 (size_t)(hh * W + ww) * 256 + ic0 + c4 * 4);
        ra[it] = v;
    }
#pragma unroll
    for (int it = 0; it < 8; it++) {
        int slot = tid + it * 256;
        int hilo = slot >> 10;
        int rowp = (slot >> 3) & 127;
        int c4 = slot & 7;
        *(float4*)(buf + hilo * HL_STRIDE + rowp * A_PITCH + c4 * 4) = ra[it];
    }

    // B phase
    constexpr int BITER = (BROWS * 16 + 255) / 256;
    float4 rb[BITER];
#pragma unroll
    for (int it = 0; it < BITER; it++) {
        int slot = tid + it * 256;
        float4 v = make_float4(0.f, 0.f, 0.f, 0.f);
        if (slot < BROWS * 16) {
            int hilo = slot / (BROWS * 8);
            int rem = slot - hilo * BROWS * 8;
            int ocr = rem >> 3, c4 = rem & 7;
            v = *(const float4*)(wb +
                ((size_t)(hilo * NSLICE + s) * WROWS + ocr0 + ocr) * 32 + c4 * 4);
        }
        rb[it] = v;
    }
#pragma unroll
    for (int it = 0; it < BITER; it++) {
        int slot = tid + it * 256;
        if (slot < BROWS * 16) {
            int hilo = slot / (BROWS * 8);
            int rem = slot - hilo * BROWS * 8;
            int ocr = rem >> 3, c4 = rem & 7;
            *(float4*)(buf + B_BASE + hilo * HL_STRIDE + ocr * A_PITCH + c4 * 4) = rb[it];
        }
    }
}

// ---------------------------------------------------------------------------
// Compute one slice (K=32 = 4 k8-steps), 3-term tf32 split.
// ---------------------------------------------------------------------------
template <int MT, int NT>
__device__ __forceinline__ void compute_slice(
    const float* __restrict__ buf, int pxw, int ocw, int g, int tg,
    float (&acc)[MT][NT][4])
{
    const uint32_t* Ab = (const uint32_t*)buf;
    const uint32_t* Bb = (const uint32_t*)(buf + B_BASE);
#pragma unroll
    for (int k8 = 0; k8 < 4; k8++) {
        const int kk = k8 * 8;
        uint32_t Ah[MT][4], Bh[NT][2];
#pragma unroll
        for (int mt = 0; mt < MT; mt++) {
            int r = (pxw + mt * 16 + g) * A_PITCH + kk + tg;
            Ah[mt][0] = Ab[r];
            Ah[mt][1] = Ab[r + 8 * A_PITCH];
            Ah[mt][2] = Ab[r + 4];
            Ah[mt][3] = Ab[r + 8 * A_PITCH + 4];
        }
#pragma unroll
        for (int nt = 0; nt < NT; nt++) {
            int q = (ocw + nt * 8 + g) * A_PITCH + kk + tg;
            Bh[nt][0] = Bb[q];
            Bh[nt][1] = Bb[q + 4];
        }
#pragma unroll
        for (int mt = 0; mt < MT; mt++)
#pragma unroll
            for (int nt = 0; nt < NT; nt++) MMA(acc[mt][nt], Ah[mt], Bh[nt]);

        uint32_t Bl[NT][2];
#pragma unroll
        for (int nt = 0; nt < NT; nt++) {
            int q = (ocw + nt * 8 + g) * A_PITCH + kk + tg + HL_STRIDE;
            Bl[nt][0] = Bb[q];
            Bl[nt][1] = Bb[q + 4];
        }
#pragma unroll
        for (int mt = 0; mt < MT; mt++)
#pragma unroll
            for (int nt = 0; nt < NT; nt++) MMA(acc[mt][nt], Ah[mt], Bl[nt]);

        uint32_t Al[MT][4];
#pragma unroll
        for (int mt = 0; mt < MT; mt++) {
            int r = (pxw + mt * 16 + g) * A_PITCH + kk + tg + HL_STRIDE;
            Al[mt][0] = Ab[r];
            Al[mt][1] = Ab[r + 8 * A_PITCH];
            Al[mt][2] = Ab[r + 4];
            Al[mt][3] = Ab[r + 8 * A_PITCH + 4];
        }
#pragma unroll
        for (int mt = 0; mt < MT; mt++)
#pragma unroll
            for (int nt = 0; nt < NT; nt++) MMA(acc[mt][nt], Al[mt], Bh[nt]);
    }
}

// ---------------------------------------------------------------------------
// Tower conv: grid (69 tiles, 2 oc-halves, 2 towers). -> g_rawD [pix][ch]
// ---------------------------------------------------------------------------
__global__ __launch_bounds__(256, 1) void tower_mma(
    int step, const float* __restrict__ bC, const float* __restrict__ bB)
{
    extern __shared__ float sm[];
    const int tid = threadIdx.x, wid = tid >> 5, lane = tid & 31;
    const int g = lane >> 2, tg = lane & 3;
    const int bx = blockIdx.x, half = blockIdx.y, t = blockIdx.z;
    const int l = lvl_of_tile(bx);
    const int pixBase = (bx - (l ? c_tcum[l - 1] : 0)) * 128;
    const int H = c_Hc[l], W = H, HW = c_HWc[l];
    const size_t lb = (size_t)c_cum[l] * 256;

    const float* ih = step ? &g_actD[t][0][lb] : &g_featD[0][lb];
    const float* il = step ? &g_actD[t][1][lb] : &g_featD[1][lb];
    const float* wb = &g_wT[t][step][0][0][0][0];
    const int ocr0 = half * 128;

    int ah[8], aw[8]; bool apv[8];
#pragma unroll
    for (int it = 0; it < 8; it++) {
        int rowp = ((tid + it * 256) >> 3) & 127;
        int pg = pixBase + rowp;
        apv[it] = pg < HW;
        ah[it] = apv[it] ? pg / W : 0;
        aw[it] = apv[it] ? pg % W : 0;
    }

    const int pxw = (wid & 1) * 64, ocw = (wid >> 1) * 32;
    float acc[4][4][4] = {};

    fill_slice<256, 128>(sm, 0, ih, il, wb, ocr0, ah, aw, apv, H, W);
    for (int s = 0; s < NSLICE; s++) {
        __syncthreads();
        if (s + 1 < NSLICE)
            fill_slice<256, 128>(sm + ((s + 1) & 1) * BUF_FLOATS, s + 1,
                                 ih, il, wb, ocr0, ah, aw, apv, H, W);
        compute_slice<4, 4>(sm + (s & 1) * BUF_FLOATS, pxw, ocw, g, tg, acc);
    }

    const float* bias = (t ? bB : bC) + step * 256;
    float* raw = &g_rawD[t][lb];
#pragma unroll
    for (int mt = 0; mt < 4; mt++) {
        int px = pixBase + pxw + mt * 16 + g;
#pragma unroll
        for (int nt = 0; nt < 4; nt++) {
            int oc = ocr0 + ocw + nt * 8 + tg * 2;
            float b0 = __ldg(&bias[oc]), b1 = __ldg(&bias[oc + 1]);
            if (px < HW)
                *(float2*)(raw + (size_t)px * 256 + oc) =
                    make_float2(acc[mt][nt][0] + b0, acc[mt][nt][1] + b1);
            if (px + 8 < HW)
                *(float2*)(raw + (size_t)(px + 8) * 256 + oc) =
                    make_float2(acc[mt][nt][2] + b0, acc[mt][nt][3] + b1);
        }
    }
}

// ---------------------------------------------------------------------------
// Score head (cls tower, 80 ch padded to 128): grid (69)
// ---------------------------------------------------------------------------
__global__ __launch_bounds__(256, 1) void head_score(
    const float* __restrict__ sb, float* __restrict__ out)
{
    extern __shared__ float sm[];
    const int tid = threadIdx.x, wid = tid >> 5, lane = tid & 31;
    const int g = lane >> 2, tg = lane & 3;
    const int bx = blockIdx.x;
    const int l = lvl_of_tile(bx);
    const int pixBase = (bx - (l ? c_tcum[l - 1] : 0)) * 128;
    const int H = c_Hc[l], W = H, HW = c_HWc[l];
    const size_t lb = (size_t)c_cum[l] * 256;

    const float* ih = &g_actD[0][0][lb];
    const float* il = &g_actD[0][1][lb];
    const float* wb = &g_wS[0][0][0][0];

    int ah[8], aw[8]; bool apv[8];
#pragma unroll
    for (int it = 0; it < 8; it++) {
        int rowp = ((tid + it * 256) >> 3) & 127;
        int pg = pixBase + rowp;
        apv[it] = pg < HW;
        ah[it] = apv[it] ? pg / W : 0;
        aw[it] = apv[it] ? pg % W : 0;
    }

    const int pxw = (wid & 1) * 64, ocw = (wid >> 1) * 32;
    float acc[4][4][4] = {};

    fill_slice<128, 128>(sm, 0, ih, il, wb, 0, ah, aw, apv, H, W);
    for (int s = 0; s < NSLICE; s++) {
        __syncthreads();
        if (s + 1 < NSLICE)
            fill_slice<128, 128>(sm + ((s + 1) & 1) * BUF_FLOATS, s + 1,
                                 ih, il, wb, 0, ah, aw, apv, H, W);
        compute_slice<4, 4>(sm + (s & 1) * BUF_FLOATS, pxw, ocw, g, tg, acc);
    }

#pragma unroll
    for (int mt = 0; mt < 4; mt++) {
        int px = pixBase + pxw + mt * 16 + g;
#pragma unroll
        for (int nt = 0; nt < 4; nt++) {
            int oc = ocw + nt * 8 + tg * 2;
            if (oc >= 80) continue;
            float b0 = __ldg(&sb[oc]), b1 = __ldg(&sb[oc + 1]);
            if (px < HW) {
                float* d = out + (size_t)(c_cum[l] + px) * 85 + oc;
                d[0] = acc[mt][nt][0] + b0;
                d[1] = acc[mt][nt][1] + b1;
            }
            if (px + 8 < HW) {
                float* d = out + (size_t)(c_cum[l] + px + 8) * 85 + oc;
                d[0] = acc[mt][nt][2] + b0;
                d[1] = acc[mt][nt][3] + b1;
            }
        }
    }
}

// ---------------------------------------------------------------------------
// Pred(4)+iou(1) head (box tower): grid (69). Warp tile 16px x 8oc.
// ---------------------------------------------------------------------------
__global__ __launch_bounds__(256, 1) void head_pred(
    const float* __restrict__ pb, const float* __restrict__ ib,
    const float* __restrict__ scales, float* __restrict__ out)
{
    extern __shared__ float sm[];
    const int tid = threadIdx.x, wid = tid >> 5, lane = tid & 31;
    const int g = lane >> 2, tg = lane & 3;
    const int bx = blockIdx.x;
    const int l = lvl_of_tile(bx);
    const int pixBase = (bx - (l ? c_tcum[l - 1] : 0)) * 128;
    const int H = c_Hc[l], W = H, HW = c_HWc[l];
    const size_t lb = (size_t)c_cum[l] * 256;

    const float* ih = &g_actD[1][0][lb];
    const float* il = &g_actD[1][1][lb];
    const float* wb = &g_wP[0][0][0][0];

    int ah[8], aw[8]; bool apv[8];
#pragma unroll
    for (int it = 0; it < 8; it++) {
        int rowp = ((tid + it * 256) >> 3) & 127;
        int pg = pixBase + rowp;
        apv[it] = pg < HW;
        ah[it] = apv[it] ? pg / W : 0;
        aw[it] = apv[it] ? pg % W : 0;
    }

    const int pxw = wid * 16;
    float acc[1][1][4] = {};

    fill_slice<8, 8>(sm, 0, ih, il, wb, 0, ah, aw, apv, H, W);
    for (int s = 0; s < NSLICE; s++) {
        __syncthreads();
        if (s + 1 < NSLICE)
            fill_slice<8, 8>(sm + ((s + 1) & 1) * BUF_FLOATS, s + 1,
                             ih, il, wb, 0, ah, aw, apv, H, W);
        compute_slice<1, 1>(sm + (s & 1) * BUF_FLOATS, pxw, 0, g, tg, acc);
    }

    float sc = __ldg(&scales[l]), sf = c_strF[l];
#pragma unroll
    for (int half = 0; half < 2; half++) {
        int px = pixBase + pxw + half * 8 + g;
        if (px >= HW) continue;
        float* d = out + (size_t)(c_cum[l] + px) * 85;
#pragma unroll
        for (int j = 0; j < 2; j++) {
            int oc = tg * 2 + j;
            float v = acc[0][0][half * 2 + j];
            if (oc < 4)
                d[80 + oc] = fmaxf((v + __ldg(&pb[oc])) * sc, 0.f) * sf;
            else if (oc == 4)
                d[84] = v + __ldg(&ib[0]);
        }
    }
}

// ---------------------------------------------------------------------------
// Weight prep (hi/lo split + reorder). 720 blocks.
// ---------------------------------------------------------------------------
__global__ __launch_bounds__(256) void wprep(
    const float* __restrict__ cw, const float* __restrict__ bw,
    const float* __restrict__ sw, const float* __restrict__ pw,
    const float* __restrict__ iw)
{
    int bx = blockIdx.x;
    if (bx < 576) {
        int t = bx / 288, step = (bx / 72) % 4, slice = bx % 72;
        int rs = slice >> 3, ic0 = (slice & 7) * 32;
        const float* src = (t ? bw : cw) + (size_t)step * 256 * 2304;
        for (int idx = threadIdx.x; idx < 256 * 32; idx += 256) {
            int oc = idx >> 5, c = idx & 31;
            float v = src[(size_t)oc * 2304 + (ic0 + c) * 9 + rs];
            float hi = f2tf32(v);
            g_wT[t][step][0][slice][oc][c] = hi;
            g_wT[t][step][1][slice][oc][c] = v - hi;
        }
    } else if (bx < 648) {
        int slice = bx - 576, rs = slice >> 3, ic0 = (slice & 7) * 32;
        for (int idx = threadIdx.x; idx < 80 * 32; idx += 256) {
            int oc = idx >> 5, c = idx & 31;
            float v = sw[(size_t)oc * 2304 + (ic0 + c) * 9 + rs];
            float hi = f2tf32(v);
            g_wS[0][slice][oc][c] = hi;
            g_wS[1][slice][oc][c] = v - hi;
        }
    } else {
        int slice = bx - 648, rs = slice >> 3, ic0 = (slice & 7) * 32;
        for (int idx = threadIdx.x; idx < 8 * 32; idx += 256) {
            int oc = idx >> 5, c = idx & 31;
            float v = 0.f;
            if (oc < 4)       v = pw[(size_t)oc * 2304 + (ic0 + c) * 9 + rs];
            else if (oc == 4) v = iw[(ic0 + c) * 9 + rs];
            float hi = f2tf32(v);
            g_wP[0][slice][oc][c] = hi;
            g_wP[1][slice][oc][c] = v - hi;
        }
    }
}

// ---------------------------------------------------------------------------
// Feature prep: NCHW -> [pix][ch] hi/lo
// ---------------------------------------------------------------------------
__global__ __launch_bounds__(256) void feat_prep(
    const float* __restrict__ f0, const float* __restrict__ f1,
    const float* __restrict__ f2, const float* __restrict__ f3,
    const float* __restrict__ f4)
{
    int l = blockIdx.y, p = blockIdx.x;
    int HW = c_HWc[l];
    if (p >= HW) return;
    const float* f = (l == 0) ? f0 : (l == 1) ? f1 : (l == 2) ? f2 : (l == 3) ? f3 : f4;
    int c = threadIdx.x;
    float v = f[(size_t)c * HW + p];
    float hi = f2tf32(v);
    size_t o = (size_t)(c_cum[l] + p) * 256 + c;
    g_featD[0][o] = hi;
    g_featD[1][o] = v - hi;
}

// ---------------------------------------------------------------------------
// GroupNorm stats: grid (32, 5, 2)
// ---------------------------------------------------------------------------
__global__ __launch_bounds__(256) void gn_stats()
{
    int g = blockIdx.x, l = blockIdx.y, t = blockIdx.z;
    int HW = c_HWc[l];
    const float* base = &g_rawD[t][(size_t)c_cum[l] * 256 + g * 8];
    float s = 0.f, ss = 0.f;
    for (int p = threadIdx.x; p < HW; p += 256) {
        const float4* q = (const float4*)(base + (size_t)p * 256);
        float4 a = q[0], b = q[1];
        s += (a.x + a.y) + (a.z + a.w) + (b.x + b.y) + (b.z + b.w);
        ss = fmaf(a.x, a.x, ss); ss = fmaf(a.y, a.y, ss);
        ss = fmaf(a.z, a.z, ss); ss = fmaf(a.w, a.w, ss);
        ss = fmaf(b.x, b.x, ss); ss = fmaf(b.y, b.y, ss);
        ss = fmaf(b.z, b.z, ss); ss = fmaf(b.w, b.w, ss);
    }
    __shared__ float sh0[256], sh1[256];
    sh0[threadIdx.x] = s; sh1[threadIdx.x] = ss;
    __syncthreads();
    for (int o = 128; o > 0; o >>= 1) {
        if (threadIdx.x < o) {
            sh0[threadIdx.x] += sh0[threadIdx.x + o];
            sh1[threadIdx.x] += sh1[threadIdx.x + o];
        }
        __syncthreads();
    }
    if (threadIdx.x == 0) {
        float inv_n = 1.f / (float)(8 * HW);
        float mean = sh0[0] * inv_n;
        float var = sh1[0] * inv_n - mean * mean;
        int si = ((t * 5 + l) * 32 + g) * 2;
        g_gst[si] = mean;
        g_gst[si + 1] = rsqrtf(fmaxf(var, 0.f) + 1e-5f);
    }
}

// ---------------------------------------------------------------------------
// GN apply + ReLU + hi/lo split: grid (NPIX, 2)
// ---------------------------------------------------------------------------
__global__ __launch_bounds__(256) void gn_apply(
    const float* __restrict__ gwC, const float* __restrict__ gbC,
    const float* __restrict__ gwB, const float* __restrict__ gbB, int step)
{
    int p = blockIdx.x, t = blockIdx.y, c = threadIdx.x;
    int l = lvl_of_pix(p);
    const float* gw = (t ? gwB : gwC) + step * 256;
    const float* gb = (t ? gbB : gbC) + step * 256;
    int si = ((t * 5 + l) * 32 + (c >> 3)) * 2;
    float mean = g_gst[si], rstd = g_gst[si + 1];
    float ga = gw[c] * rstd;
    float be = fmaf(-mean, ga, gb[c]);
    size_t o = (size_t)p * 256 + c;
    float v = fmaxf(fmaf(g_rawD[t][o], ga, be), 0.f);
    float hi = f2tf32(v);
    g_actD[t][0][o] = hi;
    g_actD[t][1][o] = v - hi;
}

// ---------------------------------------------------------------------------
// Host driver
// ---------------------------------------------------------------------------
extern "C" void kernel_launch(void* const* d_in, const int* in_sizes, int n_in,
                              void* d_out, int out_size)
{
    const float* f0 = (const float*)d_in[0];
    const float* f1 = (const float*)d_in[1];
    const float* f2 = (const float*)d_in[2];
    const float* f3 = (const float*)d_in[3];
    const float* f4 = (const float*)d_in[4];
    const float* cls_w    = (const float*)d_in[5];
    const float* cls_b    = (const float*)d_in[6];
    const float* cls_gn_w = (const float*)d_in[7];
    const float* cls_gn_b = (const float*)d_in[8];
    const float* box_w    = (const float*)d_in[9];
    const float* box_b    = (const float*)d_in[10];
    const float* box_gn_w = (const float*)d_in[11];
    const float* box_gn_b = (const float*)d_in[12];
    const float* score_w  = (const float*)d_in[13];
    const float* score_b  = (const float*)d_in[14];
    const float* pred_w   = (const float*)d_in[15];
    const float* pred_b   = (const float*)d_in[16];
    const float* iou_w    = (const float*)d_in[17];
    const float* iou_b    = (const float*)d_in[18];
    const float* scales   = (const float*)d_in[19];
    float* out = (float*)d_out;

    static bool attr_done = false;
    if (!attr_done) {
        cudaFuncSetAttribute(tower_mma, cudaFuncAttributeMaxDynamicSharedMemorySize, SMEM_BYTES);
        cudaFuncSetAttribute(head_score, cudaFuncAttributeMaxDynamicSharedMemorySize, SMEM_BYTES);
        cudaFuncSetAttribute(head_pred, cudaFuncAttributeMaxDynamicSharedMemorySize, SMEM_BYTES);
        attr_done = true;
    }

    wprep<<<720, 256>>>(cls_w, box_w, score_w, pred_w, iou_w);
    feat_prep<<<dim3(6400, 5), 256>>>(f0, f1, f2, f3, f4);

    for (int step = 0; step < 4; step++) {
        tower_mma<<<dim3(69, 2, 2), 256, SMEM_BYTES>>>(step, cls_b, box_b);
        gn_stats<<<dim3(32, 5, 2), 256>>>();
        gn_apply<<<dim3(NPIX, 2), 256>>>(cls_gn_w, cls_gn_b, box_gn_w, box_gn_b, step);
    }
    head_score<<<69, 256, SMEM_BYTES>>>(score_b, out);
    head_pred<<<69, 256, SMEM_BYTES>>>(pred_b, iou_b, scales, out);
}

// round 9
// speedup vs baseline: 4.3038x; 1.6094x over previous
#include <cuda_runtime.h>
#include <cuda_bf16.h>
#include <stdint.h>

#define CH 256
#define NPIX 8525
#define NSLICE 72

// ---- scratch (bf16 hi/lo operand storage) ---------------------------------
__device__ __align__(16) __nv_bfloat16 g_wTh[2][4][NSLICE][256][32];
__device__ __align__(16) __nv_bfloat16 g_wTl[2][4][NSLICE][256][32];
__device__ __align__(16) __nv_bfloat16 g_wSh[NSLICE][128][32];   // 80 used, rest 0
__device__ __align__(16) __nv_bfloat16 g_wSl[NSLICE][128][32];
__device__ __align__(16) __nv_bfloat16 g_wPh[NSLICE][8][32];     // pred4+iou1+pad
__device__ __align__(16) __nv_bfloat16 g_wPl[NSLICE][8][32];
__device__ __align__(16) __nv_bfloat16 g_featH[NPIX * CH];
__device__ __align__(16) __nv_bfloat16 g_featL[NPIX * CH];
__device__ __align__(16) __nv_bfloat16 g_actH[2][NPIX * CH];
__device__ __align__(16) __nv_bfloat16 g_actL[2][NPIX * CH];
__device__ float g_rawD[2][NPIX * CH];   // pre-GN fp32 [pix][ch]
__device__ float g_gst[2 * 5 * 32 * 2];

__constant__ int   c_Hc[5]   = {80, 40, 20, 10, 5};
__constant__ int   c_HWc[5]  = {6400, 1600, 400, 100, 25};
__constant__ int   c_cum[5]  = {0, 6400, 8000, 8400, 8500};
__constant__ int   c_tcum[5] = {50, 63, 67, 68, 69};
__constant__ float c_strF[5] = {8.f, 16.f, 32.f, 64.f, 128.f};

// bf16 mma: D(16x8) += A(16x16) * B(16x8)
#define MMAB(c, a, b0v, b1v) \
    asm volatile("mma.sync.aligned.m16n8k16.row.col.f32.bf16.bf16.f32 " \
        "{%0,%1,%2,%3},{%4,%5,%6,%7},{%8,%9},{%0,%1,%2,%3};" \
        : "+f"((c)[0]), "+f"((c)[1]), "+f"((c)[2]), "+f"((c)[3]) \
        : "r"((a)[0]), "r"((a)[1]), "r"((a)[2]), "r"((a)[3]), \
          "r"(b0v), "r"(b1v))

#define LDSM4(r, a) \
    asm volatile("ldmatrix.sync.aligned.m8n8.x4.shared.b16 {%0,%1,%2,%3}, [%4];" \
        : "=r"((r)[0]), "=r"((r)[1]), "=r"((r)[2]), "=r"((r)[3]) : "r"(a))

// ---- SMEM layout (u32 units): pitch 20 u32/row (conflict-free for ldmatrix)
#define PITCH 20
#define OFF_AH 0
#define OFF_AL 2560
#define OFF_BH 5120
#define OFF_BL 7680
#define BUF_U32 10240
#define SMEM_BYTES (2 * BUF_U32 * 4)   // 81920

__device__ __forceinline__ uint32_t smem_addr_of(const void* p) {
    uint32_t a;
    asm("{ .reg .u64 t; cvta.to.shared.u64 t, %1; cvt.u32.u64 %0, t; }" : "=r"(a) : "l"(p));
    return a;
}
__device__ __forceinline__ int lvl_of_tile(int bx) {
    int l = 0;
    if (bx >= c_tcum[0]) l = 1;
    if (bx >= c_tcum[1]) l = 2;
    if (bx >= c_tcum[2]) l = 3;
    if (bx >= c_tcum[3]) l = 4;
    return l;
}
__device__ __forceinline__ int lvl_of_pix(int p) {
    int l = 0;
    if (p >= 6400) l = 1;
    if (p >= 8000) l = 2;
    if (p >= 8400) l = 3;
    if (p >= 8500) l = 4;
    return l;
}

// ---------------------------------------------------------------------------
// Fill one stage: A = im2col 128px x 32ch bf16 (hi/lo), B = weights.
// BROWS_PAD rows in SMEM; rows >= BROWS_DATA are zeroed. WROWS = array stride.
// ---------------------------------------------------------------------------
template <int WROWS, int BROWS_DATA, int BROWS_PAD>
__device__ __forceinline__ void fill_slice(
    uint32_t* buf, int s,
    const __nv_bfloat16* __restrict__ ihh, const __nv_bfloat16* __restrict__ ill,
    const __nv_bfloat16* __restrict__ wh, const __nv_bfloat16* __restrict__ wl,
    int ocr0, const int* ah, const int* aw, const bool* apv, int H, int W)
{
    const int tid = threadIdx.x;
    const int rs = s >> 3, ic0 = (s & 7) * 32;
    const int dr = rs / 3 - 1, ds = rs % 3 - 1;

    // A: 1024 uint4 slots (hilo x 128 rows x 4 c8)
    uint4 ra[4];
#pragma unroll
    for (int it = 0; it < 4; it++) {
        int slot = tid + it * 256;
        int hilo = slot >> 9, c8 = slot & 3;
        int hh = ah[it] + dr, ww = aw[it] + ds;
        bool ok = apv[it] && (unsigned)hh < (unsigned)H && (unsigned)ww < (unsigned)W;
        uint4 v = make_uint4(0, 0, 0, 0);
        if (ok)
            v = *(const uint4*)((hilo ? ill : ihh) +
                                (size_t)(hh * W + ww) * 256 + ic0 + c8 * 8);
        ra[it] = v;
    }
#pragma unroll
    for (int it = 0; it < 4; it++) {
        int slot = tid + it * 256;
        int hilo = slot >> 9, rowp = (slot >> 2) & 127, c8 = slot & 3;
        *(uint4*)(buf + (hilo ? OFF_AL : OFF_AH) + rowp * PITCH + c8 * 4) = ra[it];
    }

    // B: 2*BROWS_PAD*4 uint4 slots
    constexpr int BSLOTS = 2 * BROWS_PAD * 4;
    constexpr int BITER = (BSLOTS + 255) / 256;
    uint4 rb[BITER];
#pragma unroll
    for (int it = 0; it < BITER; it++) {
        int slot = tid + it * 256;
        uint4 v = make_uint4(0, 0, 0, 0);
        if (slot < BSLOTS) {
            int hilo = slot / (BROWS_PAD * 4);
            int rem = slot - hilo * BROWS_PAD * 4;
            int ocr = rem >> 2, c8 = rem & 3;
            if (ocr < BROWS_DATA)
                v = *(const uint4*)((hilo ? wl : wh) +
                    ((size_t)s * WROWS + ocr0 + ocr) * 32 + c8 * 8);
        }
        rb[it] = v;
    }
#pragma unroll
    for (int it = 0; it < BITER; it++) {
        int slot = tid + it * 256;
        if (slot < BSLOTS) {
            int hilo = slot / (BROWS_PAD * 4);
            int rem = slot - hilo * BROWS_PAD * 4;
            int ocr = rem >> 2, c8 = rem & 3;
            *(uint4*)(buf + (hilo ? OFF_BL : OFF_BH) + ocr * PITCH + c8 * 4) = rb[it];
        }
    }
}

// ---------------------------------------------------------------------------
// Compute one slice: 2 k16-steps, 3-term bf16 split. NT even (pairs = NT/2).
// ---------------------------------------------------------------------------
template <int MT, int NT>
__device__ __forceinline__ void compute_slice(
    uint32_t bufAddr, int pxw, int ocw, float (&acc)[MT][NT][4])
{
    const int lane = threadIdx.x & 31;
    const int lrow = lane & 15, lsel = lane >> 4;
    constexpr int NP = NT / 2;
#pragma unroll
    for (int ks = 0; ks < 2; ks++) {
        const int colOff = lsel * 4 + ks * 8;
        uint32_t Ah[MT][4], Bh[NP][4];
#pragma unroll
        for (int mt = 0; mt < MT; mt++)
            LDSM4(Ah[mt], bufAddr + (((pxw + mt * 16 + lrow) * PITCH + colOff) << 2) + OFF_AH * 4);
#pragma unroll
        for (int p = 0; p < NP; p++)
            LDSM4(Bh[p], bufAddr + (((ocw + p * 16 + lrow) * PITCH + colOff) << 2) + OFF_BH * 4);
#pragma unroll
        for (int mt = 0; mt < MT; mt++)
#pragma unroll
            for (int p = 0; p < NP; p++) {
                MMAB(acc[mt][p * 2], Ah[mt], Bh[p][0], Bh[p][2]);
                MMAB(acc[mt][p * 2 + 1], Ah[mt], Bh[p][1], Bh[p][3]);
            }
        uint32_t Bl[NP][4];
#pragma unroll
        for (int p = 0; p < NP; p++)
            LDSM4(Bl[p], bufAddr + (((ocw + p * 16 + lrow) * PITCH + colOff) << 2) + OFF_BL * 4);
#pragma unroll
        for (int mt = 0; mt < MT; mt++)
#pragma unroll
            for (int p = 0; p < NP; p++) {
                MMAB(acc[mt][p * 2], Ah[mt], Bl[p][0], Bl[p][2]);
                MMAB(acc[mt][p * 2 + 1], Ah[mt], Bl[p][1], Bl[p][3]);
            }
        uint32_t Al[MT][4];
#pragma unroll
        for (int mt = 0; mt < MT; mt++)
            LDSM4(Al[mt], bufAddr + (((pxw + mt * 16 + lrow) * PITCH + colOff) << 2) + OFF_AL * 4);
#pragma unroll
        for (int mt = 0; mt < MT; mt++)
#pragma unroll
            for (int p = 0; p < NP; p++) {
                MMAB(acc[mt][p * 2], Al[mt], Bh[p][0], Bh[p][2]);
                MMAB(acc[mt][p * 2 + 1], Al[mt], Bh[p][1], Bh[p][3]);
            }
    }
}

// Common prolog: per-thread A-slot geometry
#define GEOM_PROLOG()                                                       \
    int ah[4], aw[4]; bool apv[4];                                          \
    _Pragma("unroll")                                                       \
    for (int it = 0; it < 4; it++) {                                        \
        int rowp = ((threadIdx.x + it * 256) >> 2) & 127;                   \
        int pg = pixBase + rowp;                                            \
        apv[it] = pg < HW;                                                  \
        ah[it] = apv[it] ? pg / W : 0;                                      \
        aw[it] = apv[it] ? pg % W : 0;                                      \
    }

// ---------------------------------------------------------------------------
// Tower conv: grid (69 tiles, 2 oc-halves, 2 towers)
// ---------------------------------------------------------------------------
__global__ __launch_bounds__(256, 2) void tower_mma(
    int step, const float* __restrict__ bC, const float* __restrict__ bB)
{
    extern __shared__ uint32_t sm[];
    const int tid = threadIdx.x, wid = tid >> 5, lane = tid & 31;
    const int g = lane >> 2, tg = lane & 3;
    const int bx = blockIdx.x, half = blockIdx.y, t = blockIdx.z;
    const int l = lvl_of_tile(bx);
    const int pixBase = (bx - (l ? c_tcum[l - 1] : 0)) * 128;
    const int H = c_Hc[l], W = H, HW = c_HWc[l];
    const size_t lb = (size_t)c_cum[l] * 256;

    const __nv_bfloat16* ihh = step ? &g_actH[t][lb] : &g_featH[lb];
    const __nv_bfloat16* ill = step ? &g_actL[t][lb] : &g_featL[lb];
    const __nv_bfloat16* wh = &g_wTh[t][step][0][0][0];
    const __nv_bfloat16* wl = &g_wTl[t][step][0][0][0];
    const int ocr0 = half * 128;

    GEOM_PROLOG();
    const uint32_t smA = smem_addr_of(sm);
    const int pxw = (wid & 1) * 64, ocw = (wid >> 1) * 32;
    float acc[4][4][4] = {};

    fill_slice<256, 128, 128>(sm, 0, ihh, ill, wh, wl, ocr0, ah, aw, apv, H, W);
    for (int s = 0; s < NSLICE; s++) {
        __syncthreads();
        if (s + 1 < NSLICE)
            fill_slice<256, 128, 128>(sm + ((s + 1) & 1) * BUF_U32, s + 1,
                                      ihh, ill, wh, wl, ocr0, ah, aw, apv, H, W);
        compute_slice<4, 4>(smA + ((s & 1) * BUF_U32) * 4, pxw, ocw, acc);
    }

    const float* bias = (t ? bB : bC) + step * 256;
    float* raw = &g_rawD[t][lb];
#pragma unroll
    for (int mt = 0; mt < 4; mt++) {
        int px = pixBase + pxw + mt * 16 + g;
#pragma unroll
        for (int nt = 0; nt < 4; nt++) {
            int oc = ocr0 + ocw + nt * 8 + tg * 2;
            float b0 = __ldg(&bias[oc]), b1 = __ldg(&bias[oc + 1]);
            if (px < HW)
                *(float2*)(raw + (size_t)px * 256 + oc) =
                    make_float2(acc[mt][nt][0] + b0, acc[mt][nt][1] + b1);
            if (px + 8 < HW)
                *(float2*)(raw + (size_t)(px + 8) * 256 + oc) =
                    make_float2(acc[mt][nt][2] + b0, acc[mt][nt][3] + b1);
        }
    }
}

// ---------------------------------------------------------------------------
// Score head: grid (69). 80 ch (padded to 128), cls tower -> out cols 0..79
// ---------------------------------------------------------------------------
__global__ __launch_bounds__(256, 2) void head_score(
    const float* __restrict__ sb, float* __restrict__ out)
{
    extern __shared__ uint32_t sm[];
    const int tid = threadIdx.x, wid = tid >> 5, lane = tid & 31;
    const int g = lane >> 2, tg = lane & 3;
    const int bx = blockIdx.x;
    const int l = lvl_of_tile(bx);
    const int pixBase = (bx - (l ? c_tcum[l - 1] : 0)) * 128;
    const int H = c_Hc[l], W = H, HW = c_HWc[l];
    const size_t lb = (size_t)c_cum[l] * 256;

    const __nv_bfloat16* ihh = &g_actH[0][lb];
    const __nv_bfloat16* ill = &g_actL[0][lb];

    GEOM_PROLOG();
    const uint32_t smA = smem_addr_of(sm);
    const int pxw = (wid & 1) * 64, ocw = (wid >> 1) * 32;
    float acc[4][4][4] = {};

    fill_slice<128, 128, 128>(sm, 0, ihh, ill, &g_wSh[0][0][0], &g_wSl[0][0][0],
                              0, ah, aw, apv, H, W);
    for (int s = 0; s < NSLICE; s++) {
        __syncthreads();
        if (s + 1 < NSLICE)
            fill_slice<128, 128, 128>(sm + ((s + 1) & 1) * BUF_U32, s + 1,
                                      ihh, ill, &g_wSh[0][0][0], &g_wSl[0][0][0],
                                      0, ah, aw, apv, H, W);
        compute_slice<4, 4>(smA + ((s & 1) * BUF_U32) * 4, pxw, ocw, acc);
    }

#pragma unroll
    for (int mt = 0; mt < 4; mt++) {
        int px = pixBase + pxw + mt * 16 + g;
#pragma unroll
        for (int nt = 0; nt < 4; nt++) {
            int oc = ocw + nt * 8 + tg * 2;
            if (oc >= 80) continue;
            float b0 = __ldg(&sb[oc]), b1 = __ldg(&sb[oc + 1]);
            if (px < HW) {
                float* d = out + (size_t)(c_cum[l] + px) * 85 + oc;
                d[0] = acc[mt][nt][0] + b0;
                d[1] = acc[mt][nt][1] + b1;
            }
            if (px + 8 < HW) {
                float* d = out + (size_t)(c_cum[l] + px + 8) * 85 + oc;
                d[0] = acc[mt][nt][2] + b0;
                d[1] = acc[mt][nt][3] + b1;
            }
        }
    }
}

// ---------------------------------------------------------------------------
// Pred(4)+iou(1) head: grid (69), box tower -> out cols 80..84
// ---------------------------------------------------------------------------
__global__ __launch_bounds__(256, 2) void head_pred(
    const float* __restrict__ pb, const float* __restrict__ ib,
    const float* __restrict__ scales, float* __restrict__ out)
{
    extern __shared__ uint32_t sm[];
    const int tid = threadIdx.x, wid = tid >> 5, lane = tid & 31;
    const int g = lane >> 2, tg = lane & 3;
    const int bx = blockIdx.x;
    const int l = lvl_of_tile(bx);
    const int pixBase = (bx - (l ? c_tcum[l - 1] : 0)) * 128;
    const int H = c_Hc[l], W = H, HW = c_HWc[l];
    const size_t lb = (size_t)c_cum[l] * 256;

    const __nv_bfloat16* ihh = &g_actH[1][lb];
    const __nv_bfloat16* ill = &g_actL[1][lb];

    GEOM_PROLOG();
    const uint32_t smA = smem_addr_of(sm);
    const int pxw = wid * 16;
    float acc[1][2][4] = {};

    fill_slice<8, 8, 16>(sm, 0, ihh, ill, &g_wPh[0][0][0], &g_wPl[0][0][0],
                         0, ah, aw, apv, H, W);
    for (int s = 0; s < NSLICE; s++) {
        __syncthreads();
        if (s + 1 < NSLICE)
            fill_slice<8, 8, 16>(sm + ((s + 1) & 1) * BUF_U32, s + 1,
                                 ihh, ill, &g_wPh[0][0][0], &g_wPl[0][0][0],
                                 0, ah, aw, apv, H, W);
        compute_slice<1, 2>(smA + ((s & 1) * BUF_U32) * 4, pxw, 0, acc);
    }

    float sc = __ldg(&scales[l]), sf = c_strF[l];
#pragma unroll
    for (int halfp = 0; halfp < 2; halfp++) {
        int px = pixBase + pxw + halfp * 8 + g;
        if (px >= HW) continue;
        float* d = out + (size_t)(c_cum[l] + px) * 85;
#pragma unroll
        for (int j = 0; j < 2; j++) {
            int oc = tg * 2 + j;
            float v = acc[0][0][halfp * 2 + j];
            if (oc < 4)
                d[80 + oc] = fmaxf((v + __ldg(&pb[oc])) * sc, 0.f) * sf;
            else if (oc == 4)
                d[84] = v + __ldg(&ib[0]);
        }
    }
}

// ---------------------------------------------------------------------------
// Weight prep: hi/lo bf16 split + [slice][oc][32] reorder. 720 blocks.
// ---------------------------------------------------------------------------
__global__ __launch_bounds__(256) void wprep(
    const float* __restrict__ cw, const float* __restrict__ bw,
    const float* __restrict__ sw, const float* __restrict__ pw,
    const float* __restrict__ iw)
{
    int bx = blockIdx.x;
    if (bx < 576) {
        int t = bx / 288, step = (bx / 72) % 4, slice = bx % 72;
        int rs = slice >> 3, ic0 = (slice & 7) * 32;
        const float* src = (t ? bw : cw) + (size_t)step * 256 * 2304;
        for (int idx = threadIdx.x; idx < 256 * 32; idx += 256) {
            int oc = idx >> 5, c = idx & 31;
            float v = src[(size_t)oc * 2304 + (ic0 + c) * 9 + rs];
            __nv_bfloat16 h = __float2bfloat16_rn(v);
            g_wTh[t][step][slice][oc][c] = h;
            g_wTl[t][step][slice][oc][c] = __float2bfloat16_rn(v - __bfloat162float(h));
        }
    } else if (bx < 648) {
        int slice = bx - 576, rs = slice >> 3, ic0 = (slice & 7) * 32;
        for (int idx = threadIdx.x; idx < 80 * 32; idx += 256) {
            int oc = idx >> 5, c = idx & 31;
            float v = sw[(size_t)oc * 2304 + (ic0 + c) * 9 + rs];
            __nv_bfloat16 h = __float2bfloat16_rn(v);
            g_wSh[slice][oc][c] = h;
            g_wSl[slice][oc][c] = __float2bfloat16_rn(v - __bfloat162float(h));
        }
    } else {
        int slice = bx - 648, rs = slice >> 3, ic0 = (slice & 7) * 32;
        for (int idx = threadIdx.x; idx < 8 * 32; idx += 256) {
            int oc = idx >> 5, c = idx & 31;
            float v = 0.f;
            if (oc < 4)       v = pw[(size_t)oc * 2304 + (ic0 + c) * 9 + rs];
            else if (oc == 4) v = iw[(ic0 + c) * 9 + rs];
            __nv_bfloat16 h = __float2bfloat16_rn(v);
            g_wPh[slice][oc][c] = h;
            g_wPl[slice][oc][c] = __float2bfloat16_rn(v - __bfloat162float(h));
        }
    }
}

// ---------------------------------------------------------------------------
// Feature prep: NCHW fp32 -> [pix][ch] bf16 hi/lo
// ---------------------------------------------------------------------------
__global__ __launch_bounds__(256) void feat_prep(
    const float* __restrict__ f0, const float* __restrict__ f1,
    const float* __restrict__ f2, const float* __restrict__ f3,
    const float* __restrict__ f4)
{
    int l = blockIdx.y, p = blockIdx.x;
    int HW = c_HWc[l];
    if (p >= HW) return;
    const float* f = (l == 0) ? f0 : (l == 1) ? f1 : (l == 2) ? f2 : (l == 3) ? f3 : f4;
    int c = threadIdx.x;
    float v = f[(size_t)c * HW + p];
    __nv_bfloat16 h = __float2bfloat16_rn(v);
    size_t o = (size_t)(c_cum[l] + p) * 256 + c;
    g_featH[o] = h;
    g_featL[o] = __float2bfloat16_rn(v - __bfloat162float(h));
}

// ---------------------------------------------------------------------------
// GroupNorm stats: grid (32, 5, 2)
// ---------------------------------------------------------------------------
__global__ __launch_bounds__(256) void gn_stats()
{
    int g = blockIdx.x, l = blockIdx.y, t = blockIdx.z;
    int HW = c_HWc[l];
    const float* base = &g_rawD[t][(size_t)c_cum[l] * 256 + g * 8];
    float s = 0.f, ss = 0.f;
    for (int p = threadIdx.x; p < HW; p += 256) {
        const float4* q = (const float4*)(base + (size_t)p * 256);
        float4 a = q[0], b = q[1];
        s += (a.x + a.y) + (a.z + a.w) + (b.x + b.y) + (b.z + b.w);
        ss = fmaf(a.x, a.x, ss); ss = fmaf(a.y, a.y, ss);
        ss = fmaf(a.z, a.z, ss); ss = fmaf(a.w, a.w, ss);
        ss = fmaf(b.x, b.x, ss); ss = fmaf(b.y, b.y, ss);
        ss = fmaf(b.z, b.z, ss); ss = fmaf(b.w, b.w, ss);
    }
    __shared__ float sh0[256], sh1[256];
    sh0[threadIdx.x] = s; sh1[threadIdx.x] = ss;
    __syncthreads();
    for (int o = 128; o > 0; o >>= 1) {
        if (threadIdx.x < o) {
            sh0[threadIdx.x] += sh0[threadIdx.x + o];
            sh1[threadIdx.x] += sh1[threadIdx.x + o];
        }
        __syncthreads();
    }
    if (threadIdx.x == 0) {
        float inv_n = 1.f / (float)(8 * HW);
        float mean = sh0[0] * inv_n;
        float var = sh1[0] * inv_n - mean * mean;
        int si = ((t * 5 + l) * 32 + g) * 2;
        g_gst[si] = mean;
        g_gst[si + 1] = rsqrtf(fmaxf(var, 0.f) + 1e-5f);
    }
}

// ---------------------------------------------------------------------------
// GN apply + ReLU + bf16 hi/lo split: grid (NPIX, 2)
// ---------------------------------------------------------------------------
__global__ __launch_bounds__(256) void gn_apply(
    const float* __restrict__ gwC, const float* __restrict__ gbC,
    const float* __restrict__ gwB, const float* __restrict__ gbB, int step)
{
    int p = blockIdx.x, t = blockIdx.y, c = threadIdx.x;
    int l = lvl_of_pix(p);
    const float* gw = (t ? gwB : gwC) + step * 256;
    const float* gb = (t ? gbB : gbC) + step * 256;
    int si = ((t * 5 + l) * 32 + (c >> 3)) * 2;
    float mean = g_gst[si], rstd = g_gst[si + 1];
    float ga = gw[c] * rstd;
    float be = fmaf(-mean, ga, gb[c]);
    size_t o = (size_t)p * 256 + c;
    float v = fmaxf(fmaf(g_rawD[t][o], ga, be), 0.f);
    __nv_bfloat16 h = __float2bfloat16_rn(v);
    g_actH[t][o] = h;
    g_actL[t][o] = __float2bfloat16_rn(v - __bfloat162float(h));
}

// ---------------------------------------------------------------------------
// Host driver
// ---------------------------------------------------------------------------
extern "C" void kernel_launch(void* const* d_in, const int* in_sizes, int n_in,
                              void* d_out, int out_size)
{
    const float* f0 = (const float*)d_in[0];
    const float* f1 = (const float*)d_in[1];
    const float* f2 = (const float*)d_in[2];
    const float* f3 = (const float*)d_in[3];
    const float* f4 = (const float*)d_in[4];
    const float* cls_w    = (const float*)d_in[5];
    const float* cls_b    = (const float*)d_in[6];
    const float* cls_gn_w = (const float*)d_in[7];
    const float* cls_gn_b = (const float*)d_in[8];
    const float* box_w    = (const float*)d_in[9];
    const float* box_b    = (const float*)d_in[10];
    const float* box_gn_w = (const float*)d_in[11];
    const float* box_gn_b = (const float*)d_in[12];
    const float* score_w  = (const float*)d_in[13];
    const float* score_b  = (const float*)d_in[14];
    const float* pred_w   = (const float*)d_in[15];
    const float* pred_b   = (const float*)d_in[16];
    const float* iou_w    = (const float*)d_in[17];
    const float* iou_b    = (const float*)d_in[18];
    const float* scales   = (const float*)d_in[19];
    float* out = (float*)d_out;

    static bool attr_done = false;
    if (!attr_done) {
        cudaFuncSetAttribute(tower_mma, cudaFuncAttributeMaxDynamicSharedMemorySize, SMEM_BYTES);
        cudaFuncSetAttribute(head_score, cudaFuncAttributeMaxDynamicSharedMemorySize, SMEM_BYTES);
        cudaFuncSetAttribute(head_pred, cudaFuncAttributeMaxDynamicSharedMemorySize, SMEM_BYTES);
        attr_done = true;
    }

    wprep<<<720, 256>>>(cls_w, box_w, score_w, pred_w, iou_w);
    feat_prep<<<dim3(6400, 5), 256>>>(f0, f1, f2, f3, f4);

    for (int step = 0; step < 4; step++) {
        tower_mma<<<dim3(69, 2, 2), 256, SMEM_BYTES>>>(step, cls_b, box_b);
        gn_stats<<<dim3(32, 5, 2), 256>>>();
        gn_apply<<<dim3(NPIX, 2), 256>>>(cls_gn_w, cls_gn_b, box_gn_w, box_gn_b, step);
    }
    head_score<<<69, 256, SMEM_BYTES>>>(score_b, out);
    head_pred<<<69, 256, SMEM_BYTES>>>(pred_b, iou_b, scales, out);
}

// round 10
// speedup vs baseline: 4.8042x; 1.1163x over previous
#include <cuda_runtime.h>
#include <cuda_bf16.h>
#include <stdint.h>

#define CH 256
#define NPIX 8525
#define NSLICE 72

// ---- scratch (bf16 hi/lo operand storage) ---------------------------------
__device__ __align__(16) __nv_bfloat16 g_wTh[2][4][NSLICE][256][32];
__device__ __align__(16) __nv_bfloat16 g_wTl[2][4][NSLICE][256][32];
__device__ __align__(16) __nv_bfloat16 g_wSh[NSLICE][128][32];   // 80 used
__device__ __align__(16) __nv_bfloat16 g_wSl[NSLICE][128][32];
__device__ __align__(16) __nv_bfloat16 g_wPh[NSLICE][8][32];     // pred4+iou1+pad
__device__ __align__(16) __nv_bfloat16 g_wPl[NSLICE][8][32];
__device__ __align__(16) __nv_bfloat16 g_featH[NPIX * CH];
__device__ __align__(16) __nv_bfloat16 g_featL[NPIX * CH];
__device__ __align__(16) __nv_bfloat16 g_actH[2][NPIX * CH];
__device__ __align__(16) __nv_bfloat16 g_actL[2][NPIX * CH];
__device__ float g_rawD[2][NPIX * CH];        // pre-GN fp32 [pix][ch]
__device__ float g_gsum[4][2][5][32][2];      // [step][tower][lvl][group]{s,ss}

__constant__ int   c_Hc[5]   = {80, 40, 20, 10, 5};
__constant__ int   c_HWc[5]  = {6400, 1600, 400, 100, 25};
__constant__ int   c_cum[5]  = {0, 6400, 8000, 8400, 8500};
__constant__ int   c_tcum[5] = {50, 63, 67, 68, 69};
__constant__ float c_strF[5] = {8.f, 16.f, 32.f, 64.f, 128.f};

#define MMAB(c, a, b0v, b1v) \
    asm volatile("mma.sync.aligned.m16n8k16.row.col.f32.bf16.bf16.f32 " \
        "{%0,%1,%2,%3},{%4,%5,%6,%7},{%8,%9},{%0,%1,%2,%3};" \
        : "+f"((c)[0]), "+f"((c)[1]), "+f"((c)[2]), "+f"((c)[3]) \
        : "r"((a)[0]), "r"((a)[1]), "r"((a)[2]), "r"((a)[3]), \
          "r"(b0v), "r"(b1v))

#define LDSM4(r, a) \
    asm volatile("ldmatrix.sync.aligned.m8n8.x4.shared.b16 {%0,%1,%2,%3}, [%4];" \
        : "=r"((r)[0]), "=r"((r)[1]), "=r"((r)[2]), "=r"((r)[3]) : "r"(a))

// ---- SMEM layout (u32 units): pitch 20 u32/row ----------------------------
#define PITCH 20
#define OFF_AH 0
#define OFF_AL 2560
#define OFF_BH 5120
#define OFF_BL 7680
#define BUF_U32 10240
#define SMEM_BYTES (2 * BUF_U32 * 4)   // 81920
#define WPREP_SMEM (8 * 2304 * 4)      // 73728

__device__ __forceinline__ uint32_t smem_addr_of(const void* p) {
    uint32_t a;
    asm("{ .reg .u64 t; cvta.to.shared.u64 t, %1; cvt.u32.u64 %0, t; }" : "=r"(a) : "l"(p));
    return a;
}
__device__ __forceinline__ int lvl_of_tile(int bx) {
    int l = 0;
    if (bx >= c_tcum[0]) l = 1;
    if (bx >= c_tcum[1]) l = 2;
    if (bx >= c_tcum[2]) l = 3;
    if (bx >= c_tcum[3]) l = 4;
    return l;
}
__device__ __forceinline__ int lvl_of_pix(int p) {
    int l = 0;
    if (p >= 6400) l = 1;
    if (p >= 8000) l = 2;
    if (p >= 8400) l = 3;
    if (p >= 8500) l = 4;
    return l;
}
__device__ __forceinline__ void bf_split(float v, __nv_bfloat16& h, __nv_bfloat16& lo) {
    h = __float2bfloat16_rn(v);
    lo = __float2bfloat16_rn(v - __bfloat162float(h));
}

// ---------------------------------------------------------------------------
// Fill one stage (unchanged from R9)
// ---------------------------------------------------------------------------
template <int WROWS, int BROWS_DATA, int BROWS_PAD>
__device__ __forceinline__ void fill_slice(
    uint32_t* buf, int s,
    const __nv_bfloat16* __restrict__ ihh, const __nv_bfloat16* __restrict__ ill,
    const __nv_bfloat16* __restrict__ wh, const __nv_bfloat16* __restrict__ wl,
    int ocr0, const int* ah, const int* aw, const bool* apv, int H, int W)
{
    const int tid = threadIdx.x;
    const int rs = s >> 3, ic0 = (s & 7) * 32;
    const int dr = rs / 3 - 1, ds = rs % 3 - 1;

    uint4 ra[4];
#pragma unroll
    for (int it = 0; it < 4; it++) {
        int slot = tid + it * 256;
        int hilo = slot >> 9, c8 = slot & 3;
        int hh = ah[it] + dr, ww = aw[it] + ds;
        bool ok = apv[it] && (unsigned)hh < (unsigned)H && (unsigned)ww < (unsigned)W;
        uint4 v = make_uint4(0, 0, 0, 0);
        if (ok)
            v = *(const uint4*)((hilo ? ill : ihh) +
                                (size_t)(hh * W + ww) * 256 + ic0 + c8 * 8);
        ra[it] = v;
    }
#pragma unroll
    for (int it = 0; it < 4; it++) {
        int slot = tid + it * 256;
        int hilo = slot >> 9, rowp = (slot >> 2) & 127, c8 = slot & 3;
        *(uint4*)(buf + (hilo ? OFF_AL : OFF_AH) + rowp * PITCH + c8 * 4) = ra[it];
    }

    constexpr int BSLOTS = 2 * BROWS_PAD * 4;
    constexpr int BITER = (BSLOTS + 255) / 256;
    uint4 rb[BITER];
#pragma unroll
    for (int it = 0; it < BITER; it++) {
        int slot = tid + it * 256;
        uint4 v = make_uint4(0, 0, 0, 0);
        if (slot < BSLOTS) {
            int hilo = slot / (BROWS_PAD * 4);
            int rem = slot - hilo * BROWS_PAD * 4;
            int ocr = rem >> 2, c8 = rem & 3;
            if (ocr < BROWS_DATA)
                v = *(const uint4*)((hilo ? wl : wh) +
                    ((size_t)s * WROWS + ocr0 + ocr) * 32 + c8 * 8);
        }
        rb[it] = v;
    }
#pragma unroll
    for (int it = 0; it < BITER; it++) {
        int slot = tid + it * 256;
        if (slot < BSLOTS) {
            int hilo = slot / (BROWS_PAD * 4);
            int rem = slot - hilo * BROWS_PAD * 4;
            int ocr = rem >> 2, c8 = rem & 3;
            *(uint4*)(buf + (hilo ? OFF_BL : OFF_BH) + ocr * PITCH + c8 * 4) = rb[it];
        }
    }
}

// ---------------------------------------------------------------------------
// Compute one slice (unchanged from R9)
// ---------------------------------------------------------------------------
template <int MT, int NT>
__device__ __forceinline__ void compute_slice(
    uint32_t bufAddr, int pxw, int ocw, float (&acc)[MT][NT][4])
{
    const int lane = threadIdx.x & 31;
    const int lrow = lane & 15, lsel = lane >> 4;
    constexpr int NP = NT / 2;
#pragma unroll
    for (int ks = 0; ks < 2; ks++) {
        const int colOff = lsel * 4 + ks * 8;
        uint32_t Ah[MT][4], Bh[NP][4];
#pragma unroll
        for (int mt = 0; mt < MT; mt++)
            LDSM4(Ah[mt], bufAddr + (((pxw + mt * 16 + lrow) * PITCH + colOff) << 2) + OFF_AH * 4);
#pragma unroll
        for (int p = 0; p < NP; p++)
            LDSM4(Bh[p], bufAddr + (((ocw + p * 16 + lrow) * PITCH + colOff) << 2) + OFF_BH * 4);
#pragma unroll
        for (int mt = 0; mt < MT; mt++)
#pragma unroll
            for (int p = 0; p < NP; p++) {
                MMAB(acc[mt][p * 2], Ah[mt], Bh[p][0], Bh[p][2]);
                MMAB(acc[mt][p * 2 + 1], Ah[mt], Bh[p][1], Bh[p][3]);
            }
        uint32_t Bl[NP][4];
#pragma unroll
        for (int p = 0; p < NP; p++)
            LDSM4(Bl[p], bufAddr + (((ocw + p * 16 + lrow) * PITCH + colOff) << 2) + OFF_BL * 4);
#pragma unroll
        for (int mt = 0; mt < MT; mt++)
#pragma unroll
            for (int p = 0; p < NP; p++) {
                MMAB(acc[mt][p * 2], Ah[mt], Bl[p][0], Bl[p][2]);
                MMAB(acc[mt][p * 2 + 1], Ah[mt], Bl[p][1], Bl[p][3]);
            }
        uint32_t Al[MT][4];
#pragma unroll
        for (int mt = 0; mt < MT; mt++)
            LDSM4(Al[mt], bufAddr + (((pxw + mt * 16 + lrow) * PITCH + colOff) << 2) + OFF_AL * 4);
#pragma unroll
        for (int mt = 0; mt < MT; mt++)
#pragma unroll
            for (int p = 0; p < NP; p++) {
                MMAB(acc[mt][p * 2], Al[mt], Bh[p][0], Bh[p][2]);
                MMAB(acc[mt][p * 2 + 1], Al[mt], Bh[p][1], Bh[p][3]);
            }
    }
}

#define GEOM_PROLOG()                                                       \
    int ah[4], aw[4]; bool apv[4];                                          \
    _Pragma("unroll")                                                       \
    for (int it = 0; it < 4; it++) {                                        \
        int rowp = ((threadIdx.x + it * 256) >> 2) & 127;                   \
        int pg = pixBase + rowp;                                            \
        apv[it] = pg < HW;                                                  \
        ah[it] = apv[it] ? pg / W : 0;                                      \
        aw[it] = apv[it] ? pg % W : 0;                                      \
    }

// ---------------------------------------------------------------------------
// Tower conv + fused GN-stats: grid (69, 2 halves, 2 towers)
// ---------------------------------------------------------------------------
__global__ __launch_bounds__(256, 2) void tower_mma(
    int step, const float* __restrict__ bC, const float* __restrict__ bB)
{
    extern __shared__ uint32_t sm[];
    const int tid = threadIdx.x, wid = tid >> 5, lane = tid & 31;
    const int g = lane >> 2, tg = lane & 3;
    const int bx = blockIdx.x, half = blockIdx.y, t = blockIdx.z;
    const int l = lvl_of_tile(bx);
    const int pixBase = (bx - (l ? c_tcum[l - 1] : 0)) * 128;
    const int H = c_Hc[l], W = H, HW = c_HWc[l];
    const size_t lb = (size_t)c_cum[l] * 256;

    const __nv_bfloat16* ihh = step ? &g_actH[t][lb] : &g_featH[lb];
    const __nv_bfloat16* ill = step ? &g_actL[t][lb] : &g_featL[lb];
    const __nv_bfloat16* wh = &g_wTh[t][step][0][0][0];
    const __nv_bfloat16* wl = &g_wTl[t][step][0][0][0];
    const int ocr0 = half * 128;

    GEOM_PROLOG();
    const uint32_t smA = smem_addr_of(sm);
    const int pxw = (wid & 1) * 64, ocw = (wid >> 1) * 32;
    float acc[4][4][4] = {};

    fill_slice<256, 128, 128>(sm, 0, ihh, ill, wh, wl, ocr0, ah, aw, apv, H, W);
    for (int s = 0; s < NSLICE; s++) {
        __syncthreads();
        if (s + 1 < NSLICE)
            fill_slice<256, 128, 128>(sm + ((s + 1) & 1) * BUF_U32, s + 1,
                                      ihh, ill, wh, wl, ocr0, ah, aw, apv, H, W);
        compute_slice<4, 4>(smA + ((s & 1) * BUF_U32) * 4, pxw, ocw, acc);
    }

    const float* bias = (t ? bB : bC) + step * 256;
    float* raw = &g_rawD[t][lb];
#pragma unroll
    for (int nt = 0; nt < 4; nt++) {
        int oc = ocr0 + ocw + nt * 8 + tg * 2;
        float b0 = __ldg(&bias[oc]), b1 = __ldg(&bias[oc + 1]);
        float s = 0.f, ss = 0.f;
#pragma unroll
        for (int mt = 0; mt < 4; mt++) {
            int px = pixBase + pxw + mt * 16 + g;
            float v0 = acc[mt][nt][0] + b0, v1 = acc[mt][nt][1] + b1;
            float v2 = acc[mt][nt][2] + b0, v3 = acc[mt][nt][3] + b1;
            if (px < HW) {
                *(float2*)(raw + (size_t)px * 256 + oc) = make_float2(v0, v1);
                s += v0 + v1;
                ss = fmaf(v0, v0, ss); ss = fmaf(v1, v1, ss);
            }
            if (px + 8 < HW) {
                *(float2*)(raw + (size_t)(px + 8) * 256 + oc) = make_float2(v2, v3);
                s += v2 + v3;
                ss = fmaf(v2, v2, ss); ss = fmaf(v3, v3, ss);
            }
        }
#pragma unroll
        for (int o = 16; o > 0; o >>= 1) {
            s  += __shfl_xor_sync(0xffffffffu, s, o);
            ss += __shfl_xor_sync(0xffffffffu, ss, o);
        }
        if (lane == 0) {
            int gi = (ocr0 + ocw + nt * 8) >> 3;
            atomicAdd(&g_gsum[step][t][l][gi][0], s);
            atomicAdd(&g_gsum[step][t][l][gi][1], ss);
        }
    }
}

// ---------------------------------------------------------------------------
// Merged heads: grid (69, 2). y=0 score (cls, cols 0..79); y=1 pred+iou (box)
// ---------------------------------------------------------------------------
__global__ __launch_bounds__(256, 2) void head_all(
    const float* __restrict__ sb, const float* __restrict__ pb,
    const float* __restrict__ ib, const float* __restrict__ scales,
    float* __restrict__ out)
{
    extern __shared__ uint32_t sm[];
    const int tid = threadIdx.x, wid = tid >> 5, lane = tid & 31;
    const int g = lane >> 2, tg = lane & 3;
    const int bx = blockIdx.x, mode = blockIdx.y;
    const int l = lvl_of_tile(bx);
    const int pixBase = (bx - (l ? c_tcum[l - 1] : 0)) * 128;
    const int H = c_Hc[l], W = H, HW = c_HWc[l];
    const size_t lb = (size_t)c_cum[l] * 256;

    GEOM_PROLOG();
    const uint32_t smA = smem_addr_of(sm);

    if (mode == 0) {
        const __nv_bfloat16* ihh = &g_actH[0][lb];
        const __nv_bfloat16* ill = &g_actL[0][lb];
        const int pxw = (wid & 1) * 64, ocw = (wid >> 1) * 32;
        float acc[4][4][4] = {};
        fill_slice<128, 128, 128>(sm, 0, ihh, ill, &g_wSh[0][0][0], &g_wSl[0][0][0],
                                  0, ah, aw, apv, H, W);
        for (int s = 0; s < NSLICE; s++) {
            __syncthreads();
            if (s + 1 < NSLICE)
                fill_slice<128, 128, 128>(sm + ((s + 1) & 1) * BUF_U32, s + 1,
                                          ihh, ill, &g_wSh[0][0][0], &g_wSl[0][0][0],
                                          0, ah, aw, apv, H, W);
            compute_slice<4, 4>(smA + ((s & 1) * BUF_U32) * 4, pxw, ocw, acc);
        }
#pragma unroll
        for (int mt = 0; mt < 4; mt++) {
            int px = pixBase + pxw + mt * 16 + g;
#pragma unroll
            for (int nt = 0; nt < 4; nt++) {
                int oc = ocw + nt * 8 + tg * 2;
                if (oc >= 80) continue;
                float b0 = __ldg(&sb[oc]), b1 = __ldg(&sb[oc + 1]);
                if (px < HW) {
                    float* d = out + (size_t)(c_cum[l] + px) * 85 + oc;
                    d[0] = acc[mt][nt][0] + b0;
                    d[1] = acc[mt][nt][1] + b1;
                }
                if (px + 8 < HW) {
                    float* d = out + (size_t)(c_cum[l] + px + 8) * 85 + oc;
                    d[0] = acc[mt][nt][2] + b0;
                    d[1] = acc[mt][nt][3] + b1;
                }
            }
        }
    } else {
        const __nv_bfloat16* ihh = &g_actH[1][lb];
        const __nv_bfloat16* ill = &g_actL[1][lb];
        const int pxw = wid * 16;
        float acc[1][2][4] = {};
        fill_slice<8, 8, 16>(sm, 0, ihh, ill, &g_wPh[0][0][0], &g_wPl[0][0][0],
                             0, ah, aw, apv, H, W);
        for (int s = 0; s < NSLICE; s++) {
            __syncthreads();
            if (s + 1 < NSLICE)
                fill_slice<8, 8, 16>(sm + ((s + 1) & 1) * BUF_U32, s + 1,
                                     ihh, ill, &g_wPh[0][0][0], &g_wPl[0][0][0],
                                     0, ah, aw, apv, H, W);
            compute_slice<1, 2>(smA + ((s & 1) * BUF_U32) * 4, pxw, 0, acc);
        }
        float sc = __ldg(&scales[l]), sf = c_strF[l];
#pragma unroll
        for (int halfp = 0; halfp < 2; halfp++) {
            int px = pixBase + pxw + halfp * 8 + g;
            if (px >= HW) continue;
            float* d = out + (size_t)(c_cum[l] + px) * 85;
#pragma unroll
            for (int j = 0; j < 2; j++) {
                int oc = tg * 2 + j;
                float v = acc[0][0][halfp * 2 + j];
                if (oc < 4)
                    d[80 + oc] = fmaxf((v + __ldg(&pb[oc])) * sc, 0.f) * sf;
                else if (oc == 4)
                    d[84] = v + __ldg(&ib[0]);
            }
        }
    }
}

// ---------------------------------------------------------------------------
// Weight prep, coalesced via SMEM staging. 268 blocks.
//   bx<256: towers (t, step, 8-oc chunk); 256..265: score; 266: pred; 267: zero
// ---------------------------------------------------------------------------
__global__ __launch_bounds__(256) void wprep(
    const float* __restrict__ cw, const float* __restrict__ bw,
    const float* __restrict__ sw, const float* __restrict__ pw,
    const float* __restrict__ iw)
{
    const int bx = blockIdx.x, tid = threadIdx.x;
    if (bx == 267) {
        float* z = (float*)g_gsum;
        for (int i = tid; i < 4 * 2 * 5 * 32 * 2; i += 256) z[i] = 0.f;
        return;
    }
    extern __shared__ float smw[];   // [8][2304]

    if (bx < 256) {
        int t = bx >> 7, st = (bx >> 5) & 3, oc0 = (bx & 31) * 8;
        const float* src = (t ? bw : cw) + (size_t)st * 256 * 2304 + (size_t)oc0 * 2304;
        for (int i = tid; i < 8 * 2304; i += 256) smw[i] = src[i];
        __syncthreads();
        int c = tid & 31, ocr = tid >> 5;
        for (int s = 0; s < NSLICE; s++) {
            int rs = s >> 3, ic0 = (s & 7) * 32;
            float v = smw[ocr * 2304 + (ic0 + c) * 9 + rs];
            __nv_bfloat16 h, lo; bf_split(v, h, lo);
            g_wTh[t][st][s][oc0 + ocr][c] = h;
            g_wTl[t][st][s][oc0 + ocr][c] = lo;
        }
    } else if (bx < 266) {
        int oc0 = (bx - 256) * 8;
        for (int i = tid; i < 8 * 2304; i += 256) smw[i] = sw[(size_t)oc0 * 2304 + i];
        __syncthreads();
        int c = tid & 31, ocr = tid >> 5;
        for (int s = 0; s < NSLICE; s++) {
            int rs = s >> 3, ic0 = (s & 7) * 32;
            float v = smw[ocr * 2304 + (ic0 + c) * 9 + rs];
            __nv_bfloat16 h, lo; bf_split(v, h, lo);
            g_wSh[s][oc0 + ocr][c] = h;
            g_wSl[s][oc0 + ocr][c] = lo;
        }
    } else {
        for (int i = tid; i < 8 * 2304; i += 256) {
            int r = i / 2304, k = i - r * 2304;
            float v = 0.f;
            if (r < 4) v = pw[(size_t)r * 2304 + k];
            else if (r == 4) v = iw[k];
            smw[i] = v;
        }
        __syncthreads();
        int c = tid & 31, ocr = tid >> 5;
        for (int s = 0; s < NSLICE; s++) {
            int rs = s >> 3, ic0 = (s & 7) * 32;
            float v = smw[ocr * 2304 + (ic0 + c) * 9 + rs];
            __nv_bfloat16 h, lo; bf_split(v, h, lo);
            g_wPh[s][ocr][c] = h;
            g_wPl[s][ocr][c] = lo;
        }
    }
}

// ---------------------------------------------------------------------------
// Feature prep: NCHW -> [pix][ch] bf16 hi/lo, coalesced via SMEM transpose.
// grid (200, 5), block 256. Each block: 32 px x 256 ch.
// ---------------------------------------------------------------------------
__global__ __launch_bounds__(256) void feat_prep(
    const float* __restrict__ f0, const float* __restrict__ f1,
    const float* __restrict__ f2, const float* __restrict__ f3,
    const float* __restrict__ f4)
{
    __shared__ float smf[256][33];
    const int l = blockIdx.y, tid = threadIdx.x;
    const int HW = c_HWc[l];
    const int p0 = blockIdx.x * 32;
    if (p0 >= HW) return;
    const float* f = (l == 0) ? f0 : (l == 1) ? f1 : (l == 2) ? f2 : (l == 3) ? f3 : f4;

    const int pi = tid & 31, cb = tid >> 5;
#pragma unroll 8
    for (int j = 0; j < 32; j++) {
        int c = cb + j * 8;
        smf[c][pi] = (p0 + pi < HW) ? f[(size_t)c * HW + p0 + pi] : 0.f;
    }
    __syncthreads();
#pragma unroll 4
    for (int it = 0; it < 16; it++) {
        int pl = (tid >> 7) + it * 2;
        int c2 = (tid & 127) * 2;
        int p = p0 + pl;
        if (p < HW) {
            float v0 = smf[c2][pl], v1 = smf[c2 + 1][pl];
            __nv_bfloat16 h0, l0, h1, l1;
            bf_split(v0, h0, l0);
            bf_split(v1, h1, l1);
            size_t o = (size_t)(c_cum[l] + p) * 256 + c2;
            *(__nv_bfloat162*)&g_featH[o] = __nv_bfloat162(h0, h1);
            *(__nv_bfloat162*)&g_featL[o] = __nv_bfloat162(l0, l1);
        }
    }
}

// ---------------------------------------------------------------------------
// GN apply + ReLU + bf16 split; mean/rstd from fused sums.
// grid ((NPIX+1)/2, 2), block 256 (= 2 px x 128 channel-pairs)
// ---------------------------------------------------------------------------
__global__ __launch_bounds__(256) void gn_apply(
    const float* __restrict__ gwC, const float* __restrict__ gbC,
    const float* __restrict__ gwB, const float* __restrict__ gbB, int step)
{
    const int t = blockIdx.y;
    const int p = blockIdx.x * 2 + (threadIdx.x >> 7);
    if (p >= NPIX) return;
    const int c = (threadIdx.x & 127) * 2;
    const int l = lvl_of_pix(p);
    const float* gw = (t ? gwB : gwC) + step * 256;
    const float* gb = (t ? gbB : gbC) + step * 256;

    const int gi = c >> 3;
    float s  = g_gsum[step][t][l][gi][0];
    float ss = g_gsum[step][t][l][gi][1];
    float inv_n = 1.f / (float)(8 * c_HWc[l]);
    float mean = s * inv_n;
    float var = ss * inv_n - mean * mean;
    float rstd = rsqrtf(fmaxf(var, 0.f) + 1e-5f);

    float ga0 = gw[c] * rstd,     be0 = fmaf(-mean, ga0, gb[c]);
    float ga1 = gw[c + 1] * rstd, be1 = fmaf(-mean, ga1, gb[c + 1]);

    size_t o = (size_t)p * 256 + c;
    float2 r = *(const float2*)&g_rawD[t][o];
    float v0 = fmaxf(fmaf(r.x, ga0, be0), 0.f);
    float v1 = fmaxf(fmaf(r.y, ga1, be1), 0.f);
    __nv_bfloat16 h0, l0, h1, l1;
    bf_split(v0, h0, l0);
    bf_split(v1, h1, l1);
    *(__nv_bfloat162*)&g_actH[t][o] = __nv_bfloat162(h0, h1);
    *(__nv_bfloat162*)&g_actL[t][o] = __nv_bfloat162(l0, l1);
}

// ---------------------------------------------------------------------------
// Host driver: 11 launches
// ---------------------------------------------------------------------------
extern "C" void kernel_launch(void* const* d_in, const int* in_sizes, int n_in,
                              void* d_out, int out_size)
{
    const float* f0 = (const float*)d_in[0];
    const float* f1 = (const float*)d_in[1];
    const float* f2 = (const float*)d_in[2];
    const float* f3 = (const float*)d_in[3];
    const float* f4 = (const float*)d_in[4];
    const float* cls_w    = (const float*)d_in[5];
    const float* cls_b    = (const float*)d_in[6];
    const float* cls_gn_w = (const float*)d_in[7];
    const float* cls_gn_b = (const float*)d_in[8];
    const float* box_w    = (const float*)d_in[9];
    const float* box_b    = (const float*)d_in[10];
    const float* box_gn_w = (const float*)d_in[11];
    const float* box_gn_b = (const float*)d_in[12];
    const float* score_w  = (const float*)d_in[13];
    const float* score_b  = (const float*)d_in[14];
    const float* pred_w   = (const float*)d_in[15];
    const float* pred_b   = (const float*)d_in[16];
    const float* iou_w    = (const float*)d_in[17];
    const float* iou_b    = (const float*)d_in[18];
    const float* scales   = (const float*)d_in[19];
    float* out = (float*)d_out;

    static bool attr_done = false;
    if (!attr_done) {
        cudaFuncSetAttribute(tower_mma, cudaFuncAttributeMaxDynamicSharedMemorySize, SMEM_BYTES);
        cudaFuncSetAttribute(head_all,  cudaFuncAttributeMaxDynamicSharedMemorySize, SMEM_BYTES);
        cudaFuncSetAttribute(wprep,     cudaFuncAttributeMaxDynamicSharedMemorySize, WPREP_SMEM);
        attr_done = true;
    }

    wprep<<<268, 256, WPREP_SMEM>>>(cls_w, box_w, score_w, pred_w, iou_w);
    feat_prep<<<dim3(200, 5), 256>>>(f0, f1, f2, f3, f4);

    for (int step = 0; step < 4; step++) {
        tower_mma<<<dim3(69, 2, 2), 256, SMEM_BYTES>>>(step, cls_b, box_b);
        gn_apply<<<dim3((NPIX + 1) / 2, 2), 256>>>(cls_gn_w, cls_gn_b,
                                                   box_gn_w, box_gn_b, step);
    }
    head_all<<<dim3(69, 2), 256, SMEM_BYTES>>>(score_b, pred_b, iou_b, scales, out);
}

// round 11
// speedup vs baseline: 5.2638x; 1.0957x over previous
#include <cuda_runtime.h>
#include <cuda_bf16.h>
#include <stdint.h>

#define CH 256
#define NPIX 8525
#define NSLICE 72

// ---- scratch (bf16 hi/lo operand storage) ---------------------------------
__device__ __align__(16) __nv_bfloat16 g_wTh[2][4][NSLICE][256][32];
__device__ __align__(16) __nv_bfloat16 g_wTl[2][4][NSLICE][256][32];
__device__ __align__(16) __nv_bfloat16 g_wSh[NSLICE][128][32];   // 80 used
__device__ __align__(16) __nv_bfloat16 g_wSl[NSLICE][128][32];
__device__ __align__(16) __nv_bfloat16 g_wPh[NSLICE][8][32];     // pred4+iou1+pad
__device__ __align__(16) __nv_bfloat16 g_wPl[NSLICE][8][32];
__device__ __align__(16) __nv_bfloat16 g_featH[NPIX * CH];
__device__ __align__(16) __nv_bfloat16 g_featL[NPIX * CH];
__device__ __align__(16) __nv_bfloat16 g_actH[2][NPIX * CH];
__device__ __align__(16) __nv_bfloat16 g_actL[2][NPIX * CH];
__device__ float g_rawD[2][NPIX * CH];        // pre-GN fp32 [pix][ch]
__device__ float g_gsum[4][2][5][32][2];      // [step][tower][lvl][group]{s,ss}

__constant__ int   c_Hc[5]   = {80, 40, 20, 10, 5};
__constant__ int   c_HWc[5]  = {6400, 1600, 400, 100, 25};
__constant__ int   c_cum[5]  = {0, 6400, 8000, 8400, 8500};
__constant__ int   c_tcum[5] = {50, 63, 67, 68, 69};
__constant__ float c_strF[5] = {8.f, 16.f, 32.f, 64.f, 128.f};

#define MMAB(c, a, b0v, b1v) \
    asm volatile("mma.sync.aligned.m16n8k16.row.col.f32.bf16.bf16.f32 " \
        "{%0,%1,%2,%3},{%4,%5,%6,%7},{%8,%9},{%0,%1,%2,%3};" \
        : "+f"((c)[0]), "+f"((c)[1]), "+f"((c)[2]), "+f"((c)[3]) \
        : "r"((a)[0]), "r"((a)[1]), "r"((a)[2]), "r"((a)[3]), \
          "r"(b0v), "r"(b1v))

#define LDSM4(r, a) \
    asm volatile("ldmatrix.sync.aligned.m8n8.x4.shared.b16 {%0,%1,%2,%3}, [%4];" \
        : "=r"((r)[0]), "=r"((r)[1]), "=r"((r)[2]), "=r"((r)[3]) : "r"(a))

#define CP_COMMIT() asm volatile("cp.async.commit_group;" ::: "memory")
#define CP_WAIT(n)  asm volatile("cp.async.wait_group %0;" :: "n"(n) : "memory")

__device__ __forceinline__ void cp16(uint32_t dst, const void* src, bool ok) {
    asm volatile("cp.async.cg.shared.global [%0], [%1], 16, %2;"
                 :: "r"(dst), "l"(src), "r"(ok ? 16 : 0) : "memory");
}

// ---- SMEM layout (u32 units): pitch 20 u32/row ----------------------------
#define PITCH 20
#define OFF_AH 0
#define OFF_AL 2560
#define OFF_BH 5120
#define OFF_BL 7680
#define BUF_U32 10240
#define SMEM_BYTES (2 * BUF_U32 * 4)   // 81920
#define WPREP_SMEM (8 * 2304 * 4)      // 73728

__device__ __forceinline__ uint32_t smem_addr_of(const void* p) {
    uint32_t a;
    asm("{ .reg .u64 t; cvta.to.shared.u64 t, %1; cvt.u32.u64 %0, t; }" : "=r"(a) : "l"(p));
    return a;
}
__device__ __forceinline__ int lvl_of_tile(int bx) {
    int l = 0;
    if (bx >= c_tcum[0]) l = 1;
    if (bx >= c_tcum[1]) l = 2;
    if (bx >= c_tcum[2]) l = 3;
    if (bx >= c_tcum[3]) l = 4;
    return l;
}
__device__ __forceinline__ int lvl_of_pix(int p) {
    int l = 0;
    if (p >= 6400) l = 1;
    if (p >= 8000) l = 2;
    if (p >= 8400) l = 3;
    if (p >= 8500) l = 4;
    return l;
}
__device__ __forceinline__ void bf_split(float v, __nv_bfloat16& h, __nv_bfloat16& lo) {
    h = __float2bfloat16_rn(v);
    lo = __float2bfloat16_rn(v - __bfloat162float(h));
}

// ---------------------------------------------------------------------------
// Async fill of one stage: A = im2col 128px x 32ch bf16 hi/lo, B = weights.
// bufAddr = SMEM byte address of stage base. OOB -> 16B zero-fill (src_size 0).
// ---------------------------------------------------------------------------
template <int WROWS, int BROWS_DATA, int BROWS_PAD>
__device__ __forceinline__ void fill_async(
    uint32_t bufAddr, int s,
    const __nv_bfloat16* __restrict__ ihh, const __nv_bfloat16* __restrict__ ill,
    const __nv_bfloat16* __restrict__ wh, const __nv_bfloat16* __restrict__ wl,
    int ocr0, const int* ah, const int* aw, const bool* apv, int H, int W)
{
    const int tid = threadIdx.x;
    const int rs = s >> 3, ic0 = (s & 7) * 32;
    const int dr = rs / 3 - 1, ds = rs % 3 - 1;

    // A: 1024 16B slots (hilo x 128 rows x 4 c8), 4 per thread
#pragma unroll
    for (int it = 0; it < 4; it++) {
        int slot = tid + it * 256;
        int hilo = slot >> 9, rowp = (slot >> 2) & 127, c8 = slot & 3;
        int hh = ah[it] + dr, ww = aw[it] + ds;
        bool ok = apv[it] && (unsigned)hh < (unsigned)H && (unsigned)ww < (unsigned)W;
        const __nv_bfloat16* src = (hilo ? ill : ihh) +
            (ok ? ((size_t)(hh * W + ww) * 256 + ic0 + c8 * 8) : 0);
        uint32_t dst = bufAddr +
            (((hilo ? OFF_AL : OFF_AH) + rowp * PITCH + c8 * 4) << 2);
        cp16(dst, src, ok);
    }
    // B: 2*BROWS_PAD*4 slots
    constexpr int BSLOTS = 2 * BROWS_PAD * 4;
    constexpr int BITER = (BSLOTS + 255) / 256;
#pragma unroll
    for (int it = 0; it < BITER; it++) {
        int slot = tid + it * 256;
        if (slot < BSLOTS) {
            int hilo = slot / (BROWS_PAD * 4);
            int rem = slot - hilo * BROWS_PAD * 4;
            int ocr = rem >> 2, c8 = rem & 3;
            bool ok = (ocr < BROWS_DATA);
            const __nv_bfloat16* src = (hilo ? wl : wh) +
                (ok ? (((size_t)s * WROWS + ocr0 + ocr) * 32 + c8 * 8) : 0);
            uint32_t dst = bufAddr +
                (((hilo ? OFF_BL : OFF_BH) + ocr * PITCH + c8 * 4) << 2);
            cp16(dst, src, ok);
        }
    }
}

// ---------------------------------------------------------------------------
// Compute one slice: 2 k16-steps, 3-term bf16 split.
// ---------------------------------------------------------------------------
template <int MT, int NT>
__device__ __forceinline__ void compute_slice(
    uint32_t bufAddr, int pxw, int ocw, float (&acc)[MT][NT][4])
{
    const int lane = threadIdx.x & 31;
    const int lrow = lane & 15, lsel = lane >> 4;
    constexpr int NP = NT / 2;
#pragma unroll
    for (int ks = 0; ks < 2; ks++) {
        const int colOff = lsel * 4 + ks * 8;
        uint32_t Ah[MT][4], Bh[NP][4];
#pragma unroll
        for (int mt = 0; mt < MT; mt++)
            LDSM4(Ah[mt], bufAddr + (((pxw + mt * 16 + lrow) * PITCH + colOff) << 2) + OFF_AH * 4);
#pragma unroll
        for (int p = 0; p < NP; p++)
            LDSM4(Bh[p], bufAddr + (((ocw + p * 16 + lrow) * PITCH + colOff) << 2) + OFF_BH * 4);
#pragma unroll
        for (int mt = 0; mt < MT; mt++)
#pragma unroll
            for (int p = 0; p < NP; p++) {
                MMAB(acc[mt][p * 2], Ah[mt], Bh[p][0], Bh[p][2]);
                MMAB(acc[mt][p * 2 + 1], Ah[mt], Bh[p][1], Bh[p][3]);
            }
        uint32_t Bl[NP][4];
#pragma unroll
        for (int p = 0; p < NP; p++)
            LDSM4(Bl[p], bufAddr + (((ocw + p * 16 + lrow) * PITCH + colOff) << 2) + OFF_BL * 4);
#pragma unroll
        for (int mt = 0; mt < MT; mt++)
#pragma unroll
            for (int p = 0; p < NP; p++) {
                MMAB(acc[mt][p * 2], Ah[mt], Bl[p][0], Bl[p][2]);
                MMAB(acc[mt][p * 2 + 1], Ah[mt], Bl[p][1], Bl[p][3]);
            }
        uint32_t Al[MT][4];
#pragma unroll
        for (int mt = 0; mt < MT; mt++)
            LDSM4(Al[mt], bufAddr + (((pxw + mt * 16 + lrow) * PITCH + colOff) << 2) + OFF_AL * 4);
#pragma unroll
        for (int mt = 0; mt < MT; mt++)
#pragma unroll
            for (int p = 0; p < NP; p++) {
                MMAB(acc[mt][p * 2], Al[mt], Bh[p][0], Bh[p][2]);
                MMAB(acc[mt][p * 2 + 1], Al[mt], Bh[p][1], Bh[p][3]);
            }
    }
}

#define GEOM_PROLOG()                                                       \
    int ah[4], aw[4]; bool apv[4];                                          \
    _Pragma("unroll")                                                       \
    for (int it = 0; it < 4; it++) {                                        \
        int rowp = ((threadIdx.x + it * 256) >> 2) & 127;                   \
        int pg = pixBase + rowp;                                            \
        apv[it] = pg < HW;                                                  \
        ah[it] = apv[it] ? pg / W : 0;                                      \
        aw[it] = apv[it] ? pg % W : 0;                                      \
    }

// Double-buffered cp.async mainloop (2 barriers/slice)
#define MAINLOOP(FILL_CALL_NEXT, COMPUTE_CALL)                              \
    for (int s = 0; s < NSLICE; s++) {                                      \
        __syncthreads();                                                    \
        if (s + 1 < NSLICE) {                                               \
            const int sn = s + 1;                                           \
            const uint32_t bufN = smA + ((sn & 1) * BUF_U32) * 4;           \
            FILL_CALL_NEXT;                                                 \
            CP_COMMIT();                                                    \
            CP_WAIT(1);                                                     \
        } else {                                                            \
            CP_WAIT(0);                                                     \
        }                                                                   \
        __syncthreads();                                                    \
        const uint32_t bufC = smA + ((s & 1) * BUF_U32) * 4;                \
        COMPUTE_CALL;                                                       \
    }

// ---------------------------------------------------------------------------
// Tower conv + fused GN-stats: grid (69, 2 halves, 2 towers)
// ---------------------------------------------------------------------------
__global__ __launch_bounds__(256, 2) void tower_mma(
    int step, const float* __restrict__ bC, const float* __restrict__ bB)
{
    extern __shared__ uint32_t sm[];
    const int tid = threadIdx.x, wid = tid >> 5, lane = tid & 31;
    const int g = lane >> 2, tg = lane & 3;
    const int bx = blockIdx.x, half = blockIdx.y, t = blockIdx.z;
    const int l = lvl_of_tile(bx);
    const int pixBase = (bx - (l ? c_tcum[l - 1] : 0)) * 128;
    const int H = c_Hc[l], W = H, HW = c_HWc[l];
    const size_t lb = (size_t)c_cum[l] * 256;

    const __nv_bfloat16* ihh = step ? &g_actH[t][lb] : &g_featH[lb];
    const __nv_bfloat16* ill = step ? &g_actL[t][lb] : &g_featL[lb];
    const __nv_bfloat16* wh = &g_wTh[t][step][0][0][0];
    const __nv_bfloat16* wl = &g_wTl[t][step][0][0][0];
    const int ocr0 = half * 128;

    GEOM_PROLOG();
    const uint32_t smA = smem_addr_of(sm);
    const int pxw = (wid & 1) * 64, ocw = (wid >> 1) * 32;
    float acc[4][4][4] = {};

    fill_async<256, 128, 128>(smA, 0, ihh, ill, wh, wl, ocr0, ah, aw, apv, H, W);
    CP_COMMIT();
    MAINLOOP(
        (fill_async<256, 128, 128>(bufN, sn, ihh, ill, wh, wl, ocr0, ah, aw, apv, H, W)),
        (compute_slice<4, 4>(bufC, pxw, ocw, acc)));

    const float* bias = (t ? bB : bC) + step * 256;
    float* raw = &g_rawD[t][lb];
#pragma unroll
    for (int nt = 0; nt < 4; nt++) {
        int oc = ocr0 + ocw + nt * 8 + tg * 2;
        float b0 = __ldg(&bias[oc]), b1 = __ldg(&bias[oc + 1]);
        float s = 0.f, ss = 0.f;
#pragma unroll
        for (int mt = 0; mt < 4; mt++) {
            int px = pixBase + pxw + mt * 16 + g;
            float v0 = acc[mt][nt][0] + b0, v1 = acc[mt][nt][1] + b1;
            float v2 = acc[mt][nt][2] + b0, v3 = acc[mt][nt][3] + b1;
            if (px < HW) {
                *(float2*)(raw + (size_t)px * 256 + oc) = make_float2(v0, v1);
                s += v0 + v1;
                ss = fmaf(v0, v0, ss); ss = fmaf(v1, v1, ss);
            }
            if (px + 8 < HW) {
                *(float2*)(raw + (size_t)(px + 8) * 256 + oc) = make_float2(v2, v3);
                s += v2 + v3;
                ss = fmaf(v2, v2, ss); ss = fmaf(v3, v3, ss);
            }
        }
#pragma unroll
        for (int o = 16; o > 0; o >>= 1) {
            s  += __shfl_xor_sync(0xffffffffu, s, o);
            ss += __shfl_xor_sync(0xffffffffu, ss, o);
        }
        if (lane == 0) {
            int gi = (ocr0 + ocw + nt * 8) >> 3;
            atomicAdd(&g_gsum[step][t][l][gi][0], s);
            atomicAdd(&g_gsum[step][t][l][gi][1], ss);
        }
    }
}

// ---------------------------------------------------------------------------
// Merged heads: grid (69, 2). y=0 score (cls, cols 0..79); y=1 pred+iou (box)
// ---------------------------------------------------------------------------
__global__ __launch_bounds__(256, 2) void head_all(
    const float* __restrict__ sb, const float* __restrict__ pb,
    const float* __restrict__ ib, const float* __restrict__ scales,
    float* __restrict__ out)
{
    extern __shared__ uint32_t sm[];
    const int tid = threadIdx.x, wid = tid >> 5, lane = tid & 31;
    const int g = lane >> 2, tg = lane & 3;
    const int bx = blockIdx.x, mode = blockIdx.y;
    const int l = lvl_of_tile(bx);
    const int pixBase = (bx - (l ? c_tcum[l - 1] : 0)) * 128;
    const int H = c_Hc[l], W = H, HW = c_HWc[l];
    const size_t lb = (size_t)c_cum[l] * 256;

    GEOM_PROLOG();
    const uint32_t smA = smem_addr_of(sm);

    if (mode == 0) {
        const __nv_bfloat16* ihh = &g_actH[0][lb];
        const __nv_bfloat16* ill = &g_actL[0][lb];
        const __nv_bfloat16* wh = &g_wSh[0][0][0];
        const __nv_bfloat16* wl = &g_wSl[0][0][0];
        const int pxw = (wid & 1) * 64, ocw = (wid >> 1) * 32;
        float acc[4][4][4] = {};
        fill_async<128, 128, 128>(smA, 0, ihh, ill, wh, wl, 0, ah, aw, apv, H, W);
        CP_COMMIT();
        MAINLOOP(
            (fill_async<128, 128, 128>(bufN, sn, ihh, ill, wh, wl, 0, ah, aw, apv, H, W)),
            (compute_slice<4, 4>(bufC, pxw, ocw, acc)));
#pragma unroll
        for (int mt = 0; mt < 4; mt++) {
            int px = pixBase + pxw + mt * 16 + g;
#pragma unroll
            for (int nt = 0; nt < 4; nt++) {
                int oc = ocw + nt * 8 + tg * 2;
                if (oc >= 80) continue;
                float b0 = __ldg(&sb[oc]), b1 = __ldg(&sb[oc + 1]);
                if (px < HW) {
                    float* d = out + (size_t)(c_cum[l] + px) * 85 + oc;
                    d[0] = acc[mt][nt][0] + b0;
                    d[1] = acc[mt][nt][1] + b1;
                }
                if (px + 8 < HW) {
                    float* d = out + (size_t)(c_cum[l] + px + 8) * 85 + oc;
                    d[0] = acc[mt][nt][2] + b0;
                    d[1] = acc[mt][nt][3] + b1;
                }
            }
        }
    } else {
        const __nv_bfloat16* ihh = &g_actH[1][lb];
        const __nv_bfloat16* ill = &g_actL[1][lb];
        const __nv_bfloat16* wh = &g_wPh[0][0][0];
        const __nv_bfloat16* wl = &g_wPl[0][0][0];
        const int pxw = wid * 16;
        float acc[1][2][4] = {};
        fill_async<8, 8, 16>(smA, 0, ihh, ill, wh, wl, 0, ah, aw, apv, H, W);
        CP_COMMIT();
        MAINLOOP(
            (fill_async<8, 8, 16>(bufN, sn, ihh, ill, wh, wl, 0, ah, aw, apv, H, W)),
            (compute_slice<1, 2>(bufC, pxw, 0, acc)));
        float sc = __ldg(&scales[l]), sf = c_strF[l];
#pragma unroll
        for (int halfp = 0; halfp < 2; halfp++) {
            int px = pixBase + pxw + halfp * 8 + g;
            if (px >= HW) continue;
            float* d = out + (size_t)(c_cum[l] + px) * 85;
#pragma unroll
            for (int j = 0; j < 2; j++) {
                int oc = tg * 2 + j;
                float v = acc[0][0][halfp * 2 + j];
                if (oc < 4)
                    d[80 + oc] = fmaxf((v + __ldg(&pb[oc])) * sc, 0.f) * sf;
                else if (oc == 4)
                    d[84] = v + __ldg(&ib[0]);
            }
        }
    }
}

// ---------------------------------------------------------------------------
// Weight prep, coalesced via SMEM staging. 268 blocks.
// ---------------------------------------------------------------------------
__global__ __launch_bounds__(256) void wprep(
    const float* __restrict__ cw, const float* __restrict__ bw,
    const float* __restrict__ sw, const float* __restrict__ pw,
    const float* __restrict__ iw)
{
    const int bx = blockIdx.x, tid = threadIdx.x;
    if (bx == 267) {
        float* z = (float*)g_gsum;
        for (int i = tid; i < 4 * 2 * 5 * 32 * 2; i += 256) z[i] = 0.f;
        return;
    }
    extern __shared__ float smw[];   // [8][2304]

    if (bx < 256) {
        int t = bx >> 7, st = (bx >> 5) & 3, oc0 = (bx & 31) * 8;
        const float* src = (t ? bw : cw) + (size_t)st * 256 * 2304 + (size_t)oc0 * 2304;
        for (int i = tid; i < 8 * 2304; i += 256) smw[i] = src[i];
        __syncthreads();
        int c = tid & 31, ocr = tid >> 5;
        for (int s = 0; s < NSLICE; s++) {
            int rs = s >> 3, ic0 = (s & 7) * 32;
            float v = smw[ocr * 2304 + (ic0 + c) * 9 + rs];
            __nv_bfloat16 h, lo; bf_split(v, h, lo);
            g_wTh[t][st][s][oc0 + ocr][c] = h;
            g_wTl[t][st][s][oc0 + ocr][c] = lo;
        }
    } else if (bx < 266) {
        int oc0 = (bx - 256) * 8;
        for (int i = tid; i < 8 * 2304; i += 256) smw[i] = sw[(size_t)oc0 * 2304 + i];
        __syncthreads();
        int c = tid & 31, ocr = tid >> 5;
        for (int s = 0; s < NSLICE; s++) {
            int rs = s >> 3, ic0 = (s & 7) * 32;
            float v = smw[ocr * 2304 + (ic0 + c) * 9 + rs];
            __nv_bfloat16 h, lo; bf_split(v, h, lo);
            g_wSh[s][oc0 + ocr][c] = h;
            g_wSl[s][oc0 + ocr][c] = lo;
        }
    } else {
        for (int i = tid; i < 8 * 2304; i += 256) {
            int r = i / 2304, k = i - r * 2304;
            float v = 0.f;
            if (r < 4) v = pw[(size_t)r * 2304 + k];
            else if (r == 4) v = iw[k];
            smw[i] = v;
        }
        __syncthreads();
        int c = tid & 31, ocr = tid >> 5;
        for (int s = 0; s < NSLICE; s++) {
            int rs = s >> 3, ic0 = (s & 7) * 32;
            float v = smw[ocr * 2304 + (ic0 + c) * 9 + rs];
            __nv_bfloat16 h, lo; bf_split(v, h, lo);
            g_wPh[s][ocr][c] = h;
            g_wPl[s][ocr][c] = lo;
        }
    }
}

// ---------------------------------------------------------------------------
// Feature prep: NCHW -> [pix][ch] bf16 hi/lo, coalesced via SMEM transpose.
// ---------------------------------------------------------------------------
__global__ __launch_bounds__(256) void feat_prep(
    const float* __restrict__ f0, const float* __restrict__ f1,
    const float* __restrict__ f2, const float* __restrict__ f3,
    const float* __restrict__ f4)
{
    __shared__ float smf[256][33];
    const int l = blockIdx.y, tid = threadIdx.x;
    const int HW = c_HWc[l];
    const int p0 = blockIdx.x * 32;
    if (p0 >= HW) return;
    const float* f = (l == 0) ? f0 : (l == 1) ? f1 : (l == 2) ? f2 : (l == 3) ? f3 : f4;

    const int pi = tid & 31, cb = tid >> 5;
#pragma unroll 8
    for (int j = 0; j < 32; j++) {
        int c = cb + j * 8;
        smf[c][pi] = (p0 + pi < HW) ? f[(size_t)c * HW + p0 + pi] : 0.f;
    }
    __syncthreads();
#pragma unroll 4
    for (int it = 0; it < 16; it++) {
        int pl = (tid >> 7) + it * 2;
        int c2 = (tid & 127) * 2;
        int p = p0 + pl;
        if (p < HW) {
            float v0 = smf[c2][pl], v1 = smf[c2 + 1][pl];
            __nv_bfloat16 h0, l0, h1, l1;
            bf_split(v0, h0, l0);
            bf_split(v1, h1, l1);
            size_t o = (size_t)(c_cum[l] + p) * 256 + c2;
            *(__nv_bfloat162*)&g_featH[o] = __nv_bfloat162(h0, h1);
            *(__nv_bfloat162*)&g_featL[o] = __nv_bfloat162(l0, l1);
        }
    }
}

// ---------------------------------------------------------------------------
// GN apply + ReLU + bf16 split; mean/rstd from fused sums.
// ---------------------------------------------------------------------------
__global__ __launch_bounds__(256) void gn_apply(
    const float* __restrict__ gwC, const float* __restrict__ gbC,
    const float* __restrict__ gwB, const float* __restrict__ gbB, int step)
{
    const int t = blockIdx.y;
    const int p = blockIdx.x * 2 + (threadIdx.x >> 7);
    if (p >= NPIX) return;
    const int c = (threadIdx.x & 127) * 2;
    const int l = lvl_of_pix(p);
    const float* gw = (t ? gwB : gwC) + step * 256;
    const float* gb = (t ? gbB : gbC) + step * 256;

    const int gi = c >> 3;
    float s  = g_gsum[step][t][l][gi][0];
    float ss = g_gsum[step][t][l][gi][1];
    float inv_n = 1.f / (float)(8 * c_HWc[l]);
    float mean = s * inv_n;
    float var = ss * inv_n - mean * mean;
    float rstd = rsqrtf(fmaxf(var, 0.f) + 1e-5f);

    float ga0 = gw[c] * rstd,     be0 = fmaf(-mean, ga0, gb[c]);
    float ga1 = gw[c + 1] * rstd, be1 = fmaf(-mean, ga1, gb[c + 1]);

    size_t o = (size_t)p * 256 + c;
    float2 r = *(const float2*)&g_rawD[t][o];
    float v0 = fmaxf(fmaf(r.x, ga0, be0), 0.f);
    float v1 = fmaxf(fmaf(r.y, ga1, be1), 0.f);
    __nv_bfloat16 h0, l0, h1, l1;
    bf_split(v0, h0, l0);
    bf_split(v1, h1, l1);
    *(__nv_bfloat162*)&g_actH[t][o] = __nv_bfloat162(h0, h1);
    *(__nv_bfloat162*)&g_actL[t][o] = __nv_bfloat162(l0, l1);
}

// ---------------------------------------------------------------------------
// Host driver: 11 launches
// ---------------------------------------------------------------------------
extern "C" void kernel_launch(void* const* d_in, const int* in_sizes, int n_in,
                              void* d_out, int out_size)
{
    const float* f0 = (const float*)d_in[0];
    const float* f1 = (const float*)d_in[1];
    const float* f2 = (const float*)d_in[2];
    const float* f3 = (const float*)d_in[3];
    const float* f4 = (const float*)d_in[4];
    const float* cls_w    = (const float*)d_in[5];
    const float* cls_b    = (const float*)d_in[6];
    const float* cls_gn_w = (const float*)d_in[7];
    const float* cls_gn_b = (const float*)d_in[8];
    const float* box_w    = (const float*)d_in[9];
    const float* box_b    = (const float*)d_in[10];
    const float* box_gn_w = (const float*)d_in[11];
    const float* box_gn_b = (const float*)d_in[12];
    const float* score_w  = (const float*)d_in[13];
    const float* score_b  = (const float*)d_in[14];
    const float* pred_w   = (const float*)d_in[15];
    const float* pred_b   = (const float*)d_in[16];
    const float* iou_w    = (const float*)d_in[17];
    const float* iou_b    = (const float*)d_in[18];
    const float* scales   = (const float*)d_in[19];
    float* out = (float*)d_out;

    static bool attr_done = false;
    if (!attr_done) {
        cudaFuncSetAttribute(tower_mma, cudaFuncAttributeMaxDynamicSharedMemorySize, SMEM_BYTES);
        cudaFuncSetAttribute(head_all,  cudaFuncAttributeMaxDynamicSharedMemorySize, SMEM_BYTES);
        cudaFuncSetAttribute(wprep,     cudaFuncAttributeMaxDynamicSharedMemorySize, WPREP_SMEM);
        attr_done = true;
    }

    wprep<<<268, 256, WPREP_SMEM>>>(cls_w, box_w, score_w, pred_w, iou_w);
    feat_prep<<<dim3(200, 5), 256>>>(f0, f1, f2, f3, f4);

    for (int step = 0; step < 4; step++) {
        tower_mma<<<dim3(69, 2, 2), 256, SMEM_BYTES>>>(step, cls_b, box_b);
        gn_apply<<<dim3((NPIX + 1) / 2, 2), 256>>>(cls_gn_w, cls_gn_b,
                                                   box_gn_w, box_gn_b, step);
    }
    head_all<<<dim3(69, 2), 256, SMEM_BYTES>>>(score_b, pred_b, iou_b, scales, out);
}

// round 12
// speedup vs baseline: 5.2867x; 1.0043x over previous
#include <cuda_runtime.h>
#include <cuda_bf16.h>
#include <stdint.h>

#define CH 256
#define NPIX 8525
#define NSLICE 72

// ---- scratch (bf16 hi/lo operand storage) ---------------------------------
__device__ __align__(16) __nv_bfloat16 g_wTh[2][4][NSLICE][256][32];
__device__ __align__(16) __nv_bfloat16 g_wTl[2][4][NSLICE][256][32];
__device__ __align__(16) __nv_bfloat16 g_wSh[NSLICE][128][32];   // 80 used
__device__ __align__(16) __nv_bfloat16 g_wSl[NSLICE][128][32];
__device__ __align__(16) __nv_bfloat16 g_wPh[NSLICE][8][32];     // pred4+iou1+pad
__device__ __align__(16) __nv_bfloat16 g_wPl[NSLICE][8][32];
__device__ __align__(16) __nv_bfloat16 g_featH[NPIX * CH];
__device__ __align__(16) __nv_bfloat16 g_featL[NPIX * CH];
__device__ __align__(16) __nv_bfloat16 g_actH[2][NPIX * CH];
__device__ __align__(16) __nv_bfloat16 g_actL[2][NPIX * CH];
__device__ float g_rawD[2][NPIX * CH];        // pre-GN fp32 [pix][ch]
__device__ float g_gsum[4][2][5][32][2];      // [step][tower][lvl][group]{s,ss}

__constant__ int   c_Hc[5]   = {80, 40, 20, 10, 5};
__constant__ int   c_HWc[5]  = {6400, 1600, 400, 100, 25};
__constant__ int   c_cum[5]  = {0, 6400, 8000, 8400, 8500};
__constant__ int   c_tcum[5] = {50, 63, 67, 68, 69};
__constant__ float c_strF[5] = {8.f, 16.f, 32.f, 64.f, 128.f};

#define MMAB(c, a, b0v, b1v) \
    asm volatile("mma.sync.aligned.m16n8k16.row.col.f32.bf16.bf16.f32 " \
        "{%0,%1,%2,%3},{%4,%5,%6,%7},{%8,%9},{%0,%1,%2,%3};" \
        : "+f"((c)[0]), "+f"((c)[1]), "+f"((c)[2]), "+f"((c)[3]) \
        : "r"((a)[0]), "r"((a)[1]), "r"((a)[2]), "r"((a)[3]), \
          "r"(b0v), "r"(b1v))

#define LDSM4(r, a) \
    asm volatile("ldmatrix.sync.aligned.m8n8.x4.shared.b16 {%0,%1,%2,%3}, [%4];" \
        : "=r"((r)[0]), "=r"((r)[1]), "=r"((r)[2]), "=r"((r)[3]) : "r"(a))

#define CP_COMMIT() asm volatile("cp.async.commit_group;" ::: "memory")
#define CP_WAIT(n)  asm volatile("cp.async.wait_group %0;" :: "n"(n) : "memory")

__device__ __forceinline__ void cp16(uint32_t dst, const void* src, bool ok) {
    asm volatile("cp.async.cg.shared.global [%0], [%1], 16, %2;"
                 :: "r"(dst), "l"(src), "r"(ok ? 16 : 0) : "memory");
}

// ---- SMEM layout (u32 units): pitch 20 u32/row ----------------------------
#define PITCH 20
#define OFF_AH 0
#define OFF_AL 2560
#define OFF_BH 5120
#define OFF_BL 7680
#define BUF_U32 10240
#define SMEM_BYTES (2 * BUF_U32 * 4)   // 81920
#define PREP_SMEM (8 * 2304 * 4)       // 73728

__device__ __forceinline__ uint32_t smem_addr_of(const void* p) {
    uint32_t a;
    asm("{ .reg .u64 t; cvta.to.shared.u64 t, %1; cvt.u32.u64 %0, t; }" : "=r"(a) : "l"(p));
    return a;
}
__device__ __forceinline__ int lvl_of_tile(int bx) {
    int l = 0;
    if (bx >= c_tcum[0]) l = 1;
    if (bx >= c_tcum[1]) l = 2;
    if (bx >= c_tcum[2]) l = 3;
    if (bx >= c_tcum[3]) l = 4;
    return l;
}
__device__ __forceinline__ int lvl_of_pix(int p) {
    int l = 0;
    if (p >= 6400) l = 1;
    if (p >= 8000) l = 2;
    if (p >= 8400) l = 3;
    if (p >= 8500) l = 4;
    return l;
}
__device__ __forceinline__ void bf_split(float v, __nv_bfloat16& h, __nv_bfloat16& lo) {
    h = __float2bfloat16_rn(v);
    lo = __float2bfloat16_rn(v - __bfloat162float(h));
}

// ---------------------------------------------------------------------------
// Async fill of one stage (unchanged from R11)
// ---------------------------------------------------------------------------
template <int WROWS, int BROWS_DATA, int BROWS_PAD>
__device__ __forceinline__ void fill_async(
    uint32_t bufAddr, int s,
    const __nv_bfloat16* __restrict__ ihh, const __nv_bfloat16* __restrict__ ill,
    const __nv_bfloat16* __restrict__ wh, const __nv_bfloat16* __restrict__ wl,
    int ocr0, const int* ah, const int* aw, const bool* apv, int H, int W)
{
    const int tid = threadIdx.x;
    const int rs = s >> 3, ic0 = (s & 7) * 32;
    const int dr = rs / 3 - 1, ds = rs % 3 - 1;

#pragma unroll
    for (int it = 0; it < 4; it++) {
        int slot = tid + it * 256;
        int hilo = slot >> 9, rowp = (slot >> 2) & 127, c8 = slot & 3;
        int hh = ah[it] + dr, ww = aw[it] + ds;
        bool ok = apv[it] && (unsigned)hh < (unsigned)H && (unsigned)ww < (unsigned)W;
        const __nv_bfloat16* src = (hilo ? ill : ihh) +
            (ok ? ((size_t)(hh * W + ww) * 256 + ic0 + c8 * 8) : 0);
        uint32_t dst = bufAddr +
            (((hilo ? OFF_AL : OFF_AH) + rowp * PITCH + c8 * 4) << 2);
        cp16(dst, src, ok);
    }
    constexpr int BSLOTS = 2 * BROWS_PAD * 4;
    constexpr int BITER = (BSLOTS + 255) / 256;
#pragma unroll
    for (int it = 0; it < BITER; it++) {
        int slot = tid + it * 256;
        if (slot < BSLOTS) {
            int hilo = slot / (BROWS_PAD * 4);
            int rem = slot - hilo * (BROWS_PAD * 4);
            int ocr = rem >> 2, c8 = rem & 3;
            bool ok = (ocr < BROWS_DATA);
            const __nv_bfloat16* src = (hilo ? wl : wh) +
                (ok ? (((size_t)s * WROWS + ocr0 + ocr) * 32 + c8 * 8) : 0);
            uint32_t dst = bufAddr +
                (((hilo ? OFF_BL : OFF_BH) + ocr * PITCH + c8 * 4) << 2);
            cp16(dst, src, ok);
        }
    }
}

// ---------------------------------------------------------------------------
// Compute one slice: 2 k16-steps, 3-term bf16 split.
// ---------------------------------------------------------------------------
template <int MT, int NT>
__device__ __forceinline__ void compute_slice(
    uint32_t bufAddr, int pxw, int ocw, float (&acc)[MT][NT][4])
{
    const int lane = threadIdx.x & 31;
    const int lrow = lane & 15, lsel = lane >> 4;
    constexpr int NP = NT / 2;
#pragma unroll
    for (int ks = 0; ks < 2; ks++) {
        const int colOff = lsel * 4 + ks * 8;
        uint32_t Ah[MT][4], Bh[NP][4];
#pragma unroll
        for (int mt = 0; mt < MT; mt++)
            LDSM4(Ah[mt], bufAddr + (((pxw + mt * 16 + lrow) * PITCH + colOff) << 2) + OFF_AH * 4);
#pragma unroll
        for (int p = 0; p < NP; p++)
            LDSM4(Bh[p], bufAddr + (((ocw + p * 16 + lrow) * PITCH + colOff) << 2) + OFF_BH * 4);
#pragma unroll
        for (int mt = 0; mt < MT; mt++)
#pragma unroll
            for (int p = 0; p < NP; p++) {
                MMAB(acc[mt][p * 2], Ah[mt], Bh[p][0], Bh[p][2]);
                MMAB(acc[mt][p * 2 + 1], Ah[mt], Bh[p][1], Bh[p][3]);
            }
        uint32_t Bl[NP][4];
#pragma unroll
        for (int p = 0; p < NP; p++)
            LDSM4(Bl[p], bufAddr + (((ocw + p * 16 + lrow) * PITCH + colOff) << 2) + OFF_BL * 4);
#pragma unroll
        for (int mt = 0; mt < MT; mt++)
#pragma unroll
            for (int p = 0; p < NP; p++) {
                MMAB(acc[mt][p * 2], Ah[mt], Bl[p][0], Bl[p][2]);
                MMAB(acc[mt][p * 2 + 1], Ah[mt], Bl[p][1], Bl[p][3]);
            }
        uint32_t Al[MT][4];
#pragma unroll
        for (int mt = 0; mt < MT; mt++)
            LDSM4(Al[mt], bufAddr + (((pxw + mt * 16 + lrow) * PITCH + colOff) << 2) + OFF_AL * 4);
#pragma unroll
        for (int mt = 0; mt < MT; mt++)
#pragma unroll
            for (int p = 0; p < NP; p++) {
                MMAB(acc[mt][p * 2], Al[mt], Bh[p][0], Bh[p][2]);
                MMAB(acc[mt][p * 2 + 1], Al[mt], Bh[p][1], Bh[p][3]);
            }
    }
}

#define GEOM_PROLOG()                                                       \
    int ah[4], aw[4]; bool apv[4];                                          \
    _Pragma("unroll")                                                       \
    for (int it = 0; it < 4; it++) {                                        \
        int rowp = ((threadIdx.x + it * 256) >> 2) & 127;                   \
        int pg = pixBase + rowp;                                            \
        apv[it] = pg < HW;                                                  \
        ah[it] = apv[it] ? pg / W : 0;                                      \
        aw[it] = apv[it] ? pg % W : 0;                                      \
    }

// Single-barrier double-buffered cp.async mainloop:
//   wait(fill s) -> sync -> issue fill(s+1) -> compute(s)
// The one sync covers both "fill(s) visible to all" and "all done computing
// s-1 before fill(s+1) overwrites its buffer".
#define MAINLOOP(FILL_CALL_NEXT, COMPUTE_CALL)                              \
    for (int s = 0; s < NSLICE; s++) {                                      \
        CP_WAIT(0);                                                         \
        __syncthreads();                                                    \
        if (s + 1 < NSLICE) {                                               \
            const int sn = s + 1;                                           \
            const uint32_t bufN = smA + ((sn & 1) * BUF_U32) * 4;           \
            FILL_CALL_NEXT;                                                 \
            CP_COMMIT();                                                    \
        }                                                                   \
        const uint32_t bufC = smA + ((s & 1) * BUF_U32) * 4;                \
        COMPUTE_CALL;                                                       \
    }

// ---------------------------------------------------------------------------
// Tower conv + fused GN-stats: grid (69, 2 halves, 2 towers)
// ---------------------------------------------------------------------------
__global__ __launch_bounds__(256, 2) void tower_mma(
    int step, const float* __restrict__ bC, const float* __restrict__ bB)
{
    extern __shared__ uint32_t sm[];
    const int tid = threadIdx.x, wid = tid >> 5, lane = tid & 31;
    const int g = lane >> 2, tg = lane & 3;
    const int bx = blockIdx.x, half = blockIdx.y, t = blockIdx.z;
    const int l = lvl_of_tile(bx);
    const int pixBase = (bx - (l ? c_tcum[l - 1] : 0)) * 128;
    const int H = c_Hc[l], W = H, HW = c_HWc[l];
    const size_t lb = (size_t)c_cum[l] * 256;

    const __nv_bfloat16* ihh = step ? &g_actH[t][lb] : &g_featH[lb];
    const __nv_bfloat16* ill = step ? &g_actL[t][lb] : &g_featL[lb];
    const __nv_bfloat16* wh = &g_wTh[t][step][0][0][0];
    const __nv_bfloat16* wl = &g_wTl[t][step][0][0][0];
    const int ocr0 = half * 128;

    GEOM_PROLOG();
    const uint32_t smA = smem_addr_of(sm);
    const int pxw = (wid & 1) * 64, ocw = (wid >> 1) * 32;
    float acc[4][4][4] = {};

    fill_async<256, 128, 128>(smA, 0, ihh, ill, wh, wl, ocr0, ah, aw, apv, H, W);
    CP_COMMIT();
    MAINLOOP(
        (fill_async<256, 128, 128>(bufN, sn, ihh, ill, wh, wl, ocr0, ah, aw, apv, H, W)),
        (compute_slice<4, 4>(bufC, pxw, ocw, acc)));

    const float* bias = (t ? bB : bC) + step * 256;
    float* raw = &g_rawD[t][lb];
#pragma unroll
    for (int nt = 0; nt < 4; nt++) {
        int oc = ocr0 + ocw + nt * 8 + tg * 2;
        float b0 = __ldg(&bias[oc]), b1 = __ldg(&bias[oc + 1]);
        float s = 0.f, ss = 0.f;
#pragma unroll
        for (int mt = 0; mt < 4; mt++) {
            int px = pixBase + pxw + mt * 16 + g;
            float v0 = acc[mt][nt][0] + b0, v1 = acc[mt][nt][1] + b1;
            float v2 = acc[mt][nt][2] + b0, v3 = acc[mt][nt][3] + b1;
            if (px < HW) {
                *(float2*)(raw + (size_t)px * 256 + oc) = make_float2(v0, v1);
                s += v0 + v1;
                ss = fmaf(v0, v0, ss); ss = fmaf(v1, v1, ss);
            }
            if (px + 8 < HW) {
                *(float2*)(raw + (size_t)(px + 8) * 256 + oc) = make_float2(v2, v3);
                s += v2 + v3;
                ss = fmaf(v2, v2, ss); ss = fmaf(v3, v3, ss);
            }
        }
#pragma unroll
        for (int o = 16; o > 0; o >>= 1) {
            s  += __shfl_xor_sync(0xffffffffu, s, o);
            ss += __shfl_xor_sync(0xffffffffu, ss, o);
        }
        if (lane == 0) {
            int gi = (ocr0 + ocw + nt * 8) >> 3;
            atomicAdd(&g_gsum[step][t][l][gi][0], s);
            atomicAdd(&g_gsum[step][t][l][gi][1], ss);
        }
    }
}

// ---------------------------------------------------------------------------
// Merged heads: grid (69, 2). y=0 score (cls, cols 0..79); y=1 pred+iou (box)
// ---------------------------------------------------------------------------
__global__ __launch_bounds__(256, 2) void head_all(
    const float* __restrict__ sb, const float* __restrict__ pb,
    const float* __restrict__ ib, const float* __restrict__ scales,
    float* __restrict__ out)
{
    extern __shared__ uint32_t sm[];
    const int tid = threadIdx.x, wid = tid >> 5, lane = tid & 31;
    const int g = lane >> 2, tg = lane & 3;
    const int bx = blockIdx.x, mode = blockIdx.y;
    const int l = lvl_of_tile(bx);
    const int pixBase = (bx - (l ? c_tcum[l - 1] : 0)) * 128;
    const int H = c_Hc[l], W = H, HW = c_HWc[l];
    const size_t lb = (size_t)c_cum[l] * 256;

    GEOM_PROLOG();
    const uint32_t smA = smem_addr_of(sm);

    if (mode == 0) {
        const __nv_bfloat16* ihh = &g_actH[0][lb];
        const __nv_bfloat16* ill = &g_actL[0][lb];
        const __nv_bfloat16* wh = &g_wSh[0][0][0];
        const __nv_bfloat16* wl = &g_wSl[0][0][0];
        const int pxw = (wid & 1) * 64, ocw = (wid >> 1) * 32;
        float acc[4][4][4] = {};
        fill_async<128, 128, 128>(smA, 0, ihh, ill, wh, wl, 0, ah, aw, apv, H, W);
        CP_COMMIT();
        MAINLOOP(
            (fill_async<128, 128, 128>(bufN, sn, ihh, ill, wh, wl, 0, ah, aw, apv, H, W)),
            (compute_slice<4, 4>(bufC, pxw, ocw, acc)));
#pragma unroll
        for (int mt = 0; mt < 4; mt++) {
            int px = pixBase + pxw + mt * 16 + g;
#pragma unroll
            for (int nt = 0; nt < 4; nt++) {
                int oc = ocw + nt * 8 + tg * 2;
                if (oc >= 80) continue;
                float b0 = __ldg(&sb[oc]), b1 = __ldg(&sb[oc + 1]);
                if (px < HW) {
                    float* d = out + (size_t)(c_cum[l] + px) * 85 + oc;
                    d[0] = acc[mt][nt][0] + b0;
                    d[1] = acc[mt][nt][1] + b1;
                }
                if (px + 8 < HW) {
                    float* d = out + (size_t)(c_cum[l] + px + 8) * 85 + oc;
                    d[0] = acc[mt][nt][2] + b0;
                    d[1] = acc[mt][nt][3] + b1;
                }
            }
        }
    } else {
        const __nv_bfloat16* ihh = &g_actH[1][lb];
        const __nv_bfloat16* ill = &g_actL[1][lb];
        const __nv_bfloat16* wh = &g_wPh[0][0][0];
        const __nv_bfloat16* wl = &g_wPl[0][0][0];
        const int pxw = wid * 16;
        float acc[1][2][4] = {};
        fill_async<8, 8, 16>(smA, 0, ihh, ill, wh, wl, 0, ah, aw, apv, H, W);
        CP_COMMIT();
        MAINLOOP(
            (fill_async<8, 8, 16>(bufN, sn, ihh, ill, wh, wl, 0, ah, aw, apv, H, W)),
            (compute_slice<1, 2>(bufC, pxw, 0, acc)));
        float sc = __ldg(&scales[l]), sf = c_strF[l];
#pragma unroll
        for (int halfp = 0; halfp < 2; halfp++) {
            int px = pixBase + pxw + halfp * 8 + g;
            if (px >= HW) continue;
            float* d = out + (size_t)(c_cum[l] + px) * 85;
#pragma unroll
            for (int j = 0; j < 2; j++) {
                int oc = tg * 2 + j;
                float v = acc[0][0][halfp * 2 + j];
                if (oc < 4)
                    d[80 + oc] = fmaxf((v + __ldg(&pb[oc])) * sc, 0.f) * sf;
                else if (oc == 4)
                    d[84] = v + __ldg(&ib[0]);
            }
        }
    }
}

// ---------------------------------------------------------------------------
// Combined prep: bx<268 weight prep (+zero), bx>=268 feature transpose.
// ---------------------------------------------------------------------------
__global__ __launch_bounds__(256) void prep_all(
    const float* __restrict__ cw, const float* __restrict__ bw,
    const float* __restrict__ sw, const float* __restrict__ pw,
    const float* __restrict__ iw,
    const float* __restrict__ f0, const float* __restrict__ f1,
    const float* __restrict__ f2, const float* __restrict__ f3,
    const float* __restrict__ f4)
{
    const int bx = blockIdx.x, tid = threadIdx.x;
    extern __shared__ float smw[];

    if (bx >= 268) {
        // ---- feature transpose: 32 px x 256 ch per block ----
        const int fb = bx - 268;
        const int l = fb / 200;
        const int p0 = (fb % 200) * 32;
        const int HW = c_HWc[l];
        if (p0 >= HW) return;
        const float* f = (l == 0) ? f0 : (l == 1) ? f1 : (l == 2) ? f2
                       : (l == 3) ? f3 : f4;
        float (*smf)[33] = (float (*)[33])smw;   // [256][33]
        const int pi = tid & 31, cb = tid >> 5;
#pragma unroll 8
        for (int j = 0; j < 32; j++) {
            int c = cb + j * 8;
            smf[c][pi] = (p0 + pi < HW) ? f[(size_t)c * HW + p0 + pi] : 0.f;
        }
        __syncthreads();
#pragma unroll 4
        for (int it = 0; it < 16; it++) {
            int pl = (tid >> 7) + it * 2;
            int c2 = (tid & 127) * 2;
            int p = p0 + pl;
            if (p < HW) {
                float v0 = smf[c2][pl], v1 = smf[c2 + 1][pl];
                __nv_bfloat16 h0, l0, h1, l1;
                bf_split(v0, h0, l0);
                bf_split(v1, h1, l1);
                size_t o = (size_t)(c_cum[l] + p) * 256 + c2;
                *(__nv_bfloat162*)&g_featH[o] = __nv_bfloat162(h0, h1);
                *(__nv_bfloat162*)&g_featL[o] = __nv_bfloat162(l0, l1);
            }
        }
        return;
    }
    if (bx == 267) {
        float* z = (float*)g_gsum;
        for (int i = tid; i < 4 * 2 * 5 * 32 * 2; i += 256) z[i] = 0.f;
        return;
    }
    // ---- weight prep, coalesced via SMEM staging ----
    if (bx < 256) {
        int t = bx >> 7, st = (bx >> 5) & 3, oc0 = (bx & 31) * 8;
        const float* src = (t ? bw : cw) + (size_t)st * 256 * 2304 + (size_t)oc0 * 2304;
        for (int i = tid; i < 8 * 2304; i += 256) smw[i] = src[i];
        __syncthreads();
        int c = tid & 31, ocr = tid >> 5;
        for (int s = 0; s < NSLICE; s++) {
            int rs = s >> 3, ic0 = (s & 7) * 32;
            float v = smw[ocr * 2304 + (ic0 + c) * 9 + rs];
            __nv_bfloat16 h, lo; bf_split(v, h, lo);
            g_wTh[t][st][s][oc0 + ocr][c] = h;
            g_wTl[t][st][s][oc0 + ocr][c] = lo;
        }
    } else if (bx < 266) {
        int oc0 = (bx - 256) * 8;
        for (int i = tid; i < 8 * 2304; i += 256) smw[i] = sw[(size_t)oc0 * 2304 + i];
        __syncthreads();
        int c = tid & 31, ocr = tid >> 5;
        for (int s = 0; s < NSLICE; s++) {
            int rs = s >> 3, ic0 = (s & 7) * 32;
            float v = smw[ocr * 2304 + (ic0 + c) * 9 + rs];
            __nv_bfloat16 h, lo; bf_split(v, h, lo);
            g_wSh[s][oc0 + ocr][c] = h;
            g_wSl[s][oc0 + ocr][c] = lo;
        }
    } else {
        for (int i = tid; i < 8 * 2304; i += 256) {
            int r = i / 2304, k = i - r * 2304;
            float v = 0.f;
            if (r < 4) v = pw[(size_t)r * 2304 + k];
            else if (r == 4) v = iw[k];
            smw[i] = v;
        }
        __syncthreads();
        int c = tid & 31, ocr = tid >> 5;
        for (int s = 0; s < NSLICE; s++) {
            int rs = s >> 3, ic0 = (s & 7) * 32;
            float v = smw[ocr * 2304 + (ic0 + c) * 9 + rs];
            __nv_bfloat16 h, lo; bf_split(v, h, lo);
            g_wPh[s][ocr][c] = h;
            g_wPl[s][ocr][c] = lo;
        }
    }
}

// ---------------------------------------------------------------------------
// GN apply + ReLU + bf16 split, 4 ch/thread. grid ((NPIX*64+255)/256, 2)
// ---------------------------------------------------------------------------
__global__ __launch_bounds__(256) void gn_apply(
    const float* __restrict__ gwC, const float* __restrict__ gbC,
    const float* __restrict__ gwB, const float* __restrict__ gbB, int step)
{
    const int t = blockIdx.y;
    const int idx = blockIdx.x * 256 + threadIdx.x;
    const int p = idx >> 6;
    if (p >= NPIX) return;
    const int c = (idx & 63) * 4;
    const int l = lvl_of_pix(p);
    const float* gw = (t ? gwB : gwC) + step * 256;
    const float* gb = (t ? gbB : gbC) + step * 256;

    const int gi = c >> 3;
    float s  = g_gsum[step][t][l][gi][0];
    float ss = g_gsum[step][t][l][gi][1];
    float inv_n = 1.f / (float)(8 * c_HWc[l]);
    float mean = s * inv_n;
    float var = ss * inv_n - mean * mean;
    float rstd = rsqrtf(fmaxf(var, 0.f) + 1e-5f);

    float4 gwv = *(const float4*)&gw[c];
    float4 gbv = *(const float4*)&gb[c];
    size_t o = (size_t)p * 256 + c;
    float4 r = *(const float4*)&g_rawD[t][o];

    float v0 = fmaxf(fmaf(r.x, gwv.x * rstd, fmaf(-mean, gwv.x * rstd, gbv.x)), 0.f);
    float v1 = fmaxf(fmaf(r.y, gwv.y * rstd, fmaf(-mean, gwv.y * rstd, gbv.y)), 0.f);
    float v2 = fmaxf(fmaf(r.z, gwv.z * rstd, fmaf(-mean, gwv.z * rstd, gbv.z)), 0.f);
    float v3 = fmaxf(fmaf(r.w, gwv.w * rstd, fmaf(-mean, gwv.w * rstd, gbv.w)), 0.f);

    __nv_bfloat16 h0, l0, h1, l1, h2, l2, h3, l3;
    bf_split(v0, h0, l0); bf_split(v1, h1, l1);
    bf_split(v2, h2, l2); bf_split(v3, h3, l3);
    __nv_bfloat162 hv0(h0, h1), hv1(h2, h3), lv0(l0, l1), lv1(l2, l3);
    uint32_t hu0, hu1, lu0, lu1;
    memcpy(&hu0, &hv0, 4); memcpy(&hu1, &hv1, 4);
    memcpy(&lu0, &lv0, 4); memcpy(&lu1, &lv1, 4);
    *(uint2*)&g_actH[t][o] = make_uint2(hu0, hu1);
    *(uint2*)&g_actL[t][o] = make_uint2(lu0, lu1);
}

// ---------------------------------------------------------------------------
// Host driver: 10 launches
// ---------------------------------------------------------------------------
extern "C" void kernel_launch(void* const* d_in, const int* in_sizes, int n_in,
                              void* d_out, int out_size)
{
    const float* f0 = (const float*)d_in[0];
    const float* f1 = (const float*)d_in[1];
    const float* f2 = (const float*)d_in[2];
    const float* f3 = (const float*)d_in[3];
    const float* f4 = (const float*)d_in[4];
    const float* cls_w    = (const float*)d_in[5];
    const float* cls_b    = (const float*)d_in[6];
    const float* cls_gn_w = (const float*)d_in[7];
    const float* cls_gn_b = (const float*)d_in[8];
    const float* box_w    = (const float*)d_in[9];
    const float* box_b    = (const float*)d_in[10];
    const float* box_gn_w = (const float*)d_in[11];
    const float* box_gn_b = (const float*)d_in[12];
    const float* score_w  = (const float*)d_in[13];
    const float* score_b  = (const float*)d_in[14];
    const float* pred_w   = (const float*)d_in[15];
    const float* pred_b   = (const float*)d_in[16];
    const float* iou_w    = (const float*)d_in[17];
    const float* iou_b    = (const float*)d_in[18];
    const float* scales   = (const float*)d_in[19];
    float* out = (float*)d_out;

    static bool attr_done = false;
    if (!attr_done) {
        cudaFuncSetAttribute(tower_mma, cudaFuncAttributeMaxDynamicSharedMemorySize, SMEM_BYTES);
        cudaFuncSetAttribute(head_all,  cudaFuncAttributeMaxDynamicSharedMemorySize, SMEM_BYTES);
        cudaFuncSetAttribute(prep_all,  cudaFuncAttributeMaxDynamicSharedMemorySize, PREP_SMEM);
        attr_done = true;
    }

    prep_all<<<268 + 1000, 256, PREP_SMEM>>>(cls_w, box_w, score_w, pred_w, iou_w,
                                             f0, f1, f2, f3, f4);

    for (int step = 0; step < 4; step++) {
        tower_mma<<<dim3(69, 2, 2), 256, SMEM_BYTES>>>(step, cls_b, box_b);
        gn_apply<<<dim3((NPIX * 64 + 255) / 256, 2), 256>>>(cls_gn_w, cls_gn_b,
                                                            box_gn_w, box_gn_b, step);
    }
    head_all<<<dim3(69, 2), 256, SMEM_BYTES>>>(score_b, pred_b, iou_b, scales, out);
}